// round 12
// baseline (speedup 1.0000x reference)
#include <cuda_runtime.h>
#include <cuda_bf16.h>
#include <math.h>
#include <stdint.h>

#define B_SZ   256
#define C_IN   7
#define T_LEN  160
#define PATCH  10
#define L_TK   16
#define D_MODEL 512
#define D_INNER 1024
#define D_STATE 16
#define DT_RANK 32
#define D_CONV  4
#define M_ROWS (B_SZ * L_TK)          // 4096
#define PROJW  (DT_RANK + 2*D_STATE)  // 64
#define EPS 1e-5f

// ---------------- scratch ----------------------------------------------------
__device__ float g_h  [M_ROWS * D_MODEL];
__device__ float g_uz [2 * M_ROWS * 2 * D_INNER];
__device__ float g_proj[2 * M_ROWS * PROJW];
__device__ __nv_bfloat16 g_hnb[M_ROWS * D_MODEL];
__device__ __nv_bfloat16 g_ucb[2 * M_ROWS * D_INNER];        // bf16 uc for x_proj
__device__ __nv_bfloat16 g_ysb[M_ROWS * 2 * D_INNER];        // [row][dir*1024+d]
__device__ __nv_bfloat16 g_wib[4 * 2 * D_INNER * D_MODEL];   // 4 x [2048][512]
__device__ __nv_bfloat16 g_wob[2 * 2 * D_INNER * D_MODEL];   // 2 x [512][2048]
__device__ __nv_bfloat16 g_wxb[4 * PROJW * D_INNER];         // 4 x [64][1024]

// ---------------- helpers ----------------------------------------------------
__device__ __forceinline__ void mma16(float* c, const uint32_t* a, const uint32_t* b) {
    asm volatile(
        "mma.sync.aligned.m16n8k16.row.col.f32.bf16.bf16.f32 "
        "{%0,%1,%2,%3},{%4,%5,%6,%7},{%8,%9},{%0,%1,%2,%3};"
        : "+f"(c[0]), "+f"(c[1]), "+f"(c[2]), "+f"(c[3])
        : "r"(a[0]), "r"(a[1]), "r"(a[2]), "r"(a[3]), "r"(b[0]), "r"(b[1]));
}
__device__ __forceinline__ void ldsm4(uint32_t& r0, uint32_t& r1, uint32_t& r2,
                                      uint32_t& r3, uint32_t addr) {
    asm volatile("ldmatrix.sync.aligned.m8n8.x4.shared.b16 {%0,%1,%2,%3}, [%4];"
                 : "=r"(r0), "=r"(r1), "=r"(r2), "=r"(r3) : "r"(addr));
}
__device__ __forceinline__ float softplusf(float v) {
    return fmaxf(v, 0.f) + log1pf(__expf(-fabsf(v)));
}
__device__ __forceinline__ void cp16(void* dst, const void* src) {
    uint32_t d = (uint32_t)__cvta_generic_to_shared(dst);
    asm volatile("cp.async.cg.shared.global [%0], [%1], 16;" :: "r"(d), "l"(src));
}
#define CP_COMMIT() asm volatile("cp.async.commit_group;")
#define CP_WAIT2()  asm volatile("cp.async.wait_group 2;")

typedef unsigned long long ull;
__device__ __forceinline__ ull pk2(float x, float y) {
    ull r; asm("mov.b64 %0, {%1,%2};" : "=l"(r) : "f"(x), "f"(y)); return r;
}
__device__ __forceinline__ void upk2(ull v, float& x, float& y) {
    asm("mov.b64 {%0,%1}, %2;" : "=f"(x), "=f"(y) : "l"(v));
}
__device__ __forceinline__ ull fma2(ull a, ull b, ull c) {
    ull d; asm("fma.rn.f32x2 %0, %1, %2, %3;" : "=l"(d) : "l"(a), "l"(b), "l"(c)); return d;
}
__device__ __forceinline__ ull mul2(ull a, ull b) {
    ull d; asm("mul.rn.f32x2 %0, %1, %2;" : "=l"(d) : "l"(a), "l"(b)); return d;
}

__device__ __forceinline__ float block_sum_512(float v, float* sm) {
    int tid = threadIdx.x;
    #pragma unroll
    for (int o = 16; o; o >>= 1) v += __shfl_xor_sync(0xffffffffu, v, o);
    if ((tid & 31) == 0) sm[tid >> 5] = v;
    __syncthreads();
    if (tid == 0) {
        float s = 0.f;
        #pragma unroll
        for (int i = 0; i < 16; i++) s += sm[i];
        sm[16] = s;
    }
    __syncthreads();
    float r = sm[16];
    __syncthreads();
    return r;
}

// ---------------- transpose + convert weights to bf16 ------------------------
__global__ void k_tb(const float* __restrict__ src, __nv_bfloat16* __restrict__ dst,
                     int K, int N) {
    __shared__ __nv_bfloat16 t[32][33];
    long zo = (long)blockIdx.z * K * N;
    int n0 = blockIdx.x * 32, k0 = blockIdx.y * 32;
    for (int i = threadIdx.y; i < 32; i += 8)
        t[i][threadIdx.x] = __float2bfloat16(src[zo + (size_t)(k0 + i) * N + n0 + threadIdx.x]);
    __syncthreads();
    for (int i = threadIdx.y; i < 32; i += 8)
        dst[zo + (size_t)(n0 + i) * K + k0 + threadIdx.x] = t[threadIdx.x][i];
}

// ---------------- 3-stage bf16 MMA GEMM with ldmatrix ------------------------
// A [M][K] bf16 row-major, B [N][K] bf16 row-major (pre-transposed weights).
// EPI: 0 = store fp32, 2 = accumulate fp32. Dynamic smem (3 stages).
template<int BM, int BN, int WARPS_M, int WARPS_N, int EPI>
__global__ void __launch_bounds__(WARPS_M * WARPS_N * 32)
k_mmab(const __nv_bfloat16* __restrict__ A, int lda, long strideAz,
       const __nv_bfloat16* __restrict__ Bg, int ldb, long strideBz,
       float* __restrict__ C, int ldc, long strideCz, int K) {
    constexpr int BK = 32;
    constexpr int LDP = 20;               // 80B row stride: 16B aligned, conflict-free
    constexpr int NS  = 3;
    constexpr int T  = WARPS_M * WARPS_N * 32;
    constexpr int WTM = BM / WARPS_M;
    constexpr int WTN = BN / WARPS_N;
    constexpr int MT  = WTM / 16;
    constexpr int NT  = WTN / 8;
    static_assert(NT % 2 == 0, "NT must be even for paired B ldmatrix");

    extern __shared__ uint32_t dyn[];
    typedef uint32_t ATile[BM][LDP];
    typedef uint32_t BTile[BN][LDP];
    ATile* As2 = (ATile*)dyn;
    BTile* Bs2 = (BTile*)(dyn + NS * BM * LDP);

    int tid = threadIdx.x, lane = tid & 31, wid = tid >> 5;
    int wm = wid % WARPS_M, wn = wid / WARPS_M;
    int m0 = blockIdx.y * BM, n0 = blockIdx.x * BN;
    int z = blockIdx.z;
    int tig = lane & 3, grp = lane >> 2;

    const __nv_bfloat16* Ap = A + (long)z * strideAz;
    const __nv_bfloat16* Bp = Bg + (long)z * strideBz;
    float* Cp = C + (long)z * strideCz;

    int a_row_off = (lane & 7) + ((lane >> 3) & 1) * 8;
    int a_col_off = ((lane >> 4) & 1) * 4;
    int b_row_off = (lane & 7) + ((lane >> 4) & 1) * 8;
    int b_col_off = ((lane >> 3) & 1) * 4;

    float acc[MT][NT][4];
    #pragma unroll
    for (int i = 0; i < MT; i++)
        #pragma unroll
        for (int j = 0; j < NT; j++)
            #pragma unroll
            for (int q = 0; q < 4; q++) acc[i][j][q] = 0.f;

    auto load_tiles = [&](int st, int k0) {
        #pragma unroll 2
        for (int idx = tid; idx < BM * 4; idx += T) {
            int m = idx >> 2, c = idx & 3;
            cp16(&As2[st][m][c * 4], Ap + (size_t)(m0 + m) * lda + k0 + c * 8);
        }
        #pragma unroll 2
        for (int idx = tid; idx < BN * 4; idx += T) {
            int n = idx >> 2, c = idx & 3;
            cp16(&Bs2[st][n][c * 4], Bp + (size_t)(n0 + n) * ldb + k0 + c * 8);
        }
    };

    int KT = K / BK;
    load_tiles(0, 0);
    CP_COMMIT();
    load_tiles(1, BK);
    CP_COMMIT();
    int st = 0;
    for (int kt = 0; kt < KT; kt++) {
        if (kt + 2 < KT) {
            int s2 = st + 2; if (s2 >= NS) s2 -= NS;
            load_tiles(s2, (kt + 2) * BK);
        }
        CP_COMMIT();
        CP_WAIT2();
        __syncthreads();

        uint32_t aBase = (uint32_t)__cvta_generic_to_shared(&As2[st][0][0]);
        uint32_t bBase = (uint32_t)__cvta_generic_to_shared(&Bs2[st][0][0]);
        #pragma unroll
        for (int ks = 0; ks < 2; ks++) {
            int pb = ks * 8;
            uint32_t afr[MT][4], bfr[NT][2];
            #pragma unroll
            for (int i = 0; i < MT; i++) {
                int r = wm * WTM + i * 16;
                uint32_t addr = aBase +
                    (uint32_t)(((r + a_row_off) * LDP + pb + a_col_off) * 4);
                ldsm4(afr[i][0], afr[i][1], afr[i][2], afr[i][3], addr);
            }
            #pragma unroll
            for (int j = 0; j < NT; j += 2) {
                int nb = wn * WTN + j * 8;
                uint32_t addr = bBase +
                    (uint32_t)(((nb + b_row_off) * LDP + pb + b_col_off) * 4);
                ldsm4(bfr[j][0], bfr[j][1], bfr[j + 1][0], bfr[j + 1][1], addr);
            }
            #pragma unroll
            for (int i = 0; i < MT; i++)
                #pragma unroll
                for (int j = 0; j < NT; j++)
                    mma16(acc[i][j], afr[i], bfr[j]);
        }
        __syncthreads();
        if (++st >= NS) st = 0;
    }

    #pragma unroll
    for (int i = 0; i < MT; i++) {
        #pragma unroll
        for (int half = 0; half < 2; half++) {
            int r = m0 + wm * WTM + i * 16 + grp + half * 8;
            #pragma unroll
            for (int j = 0; j < NT; j++) {
                int n = n0 + wn * WTN + j * 8 + tig * 2;
                float v0 = acc[i][j][half * 2 + 0];
                float v1 = acc[i][j][half * 2 + 1];
                float* cp = Cp + (size_t)r * ldc + n;
                if (EPI == 2) {
                    cp[0] += v0;
                    cp[1] += v1;
                } else {
                    *(float2*)cp = make_float2(v0, v1);
                }
            }
        }
    }
}
#define MMAB_SMEM (3 * (128 * 20 + 128 * 20) * 4)
#define XPROJ_SMEM (3 * (64 * 20 + 64 * 20) * 4)

// ---------------- patch embed + LN + pos ------------------------------------
__global__ void k_patch(const float* __restrict__ x,
                        const float* __restrict__ bng, const float* __restrict__ bnb,
                        const float* __restrict__ bnm, const float* __restrict__ bnv,
                        const float* __restrict__ pw,  const float* __restrict__ pb,
                        const float* __restrict__ lg,  const float* __restrict__ lb,
                        const float* __restrict__ pos) {
    __shared__ float p[C_IN * PATCH];
    __shared__ float sm[17];
    int row = blockIdx.x, tid = threadIdx.x;
    int b = row >> 4, l = row & 15;
    if (tid < C_IN * PATCH) {
        int c = tid / PATCH, j = tid - c * PATCH;
        float xv = x[(b * C_IN + c) * T_LEN + l * PATCH + j];
        p[tid] = (xv - bnm[c]) * rsqrtf(bnv[c] + EPS) * bng[c] + bnb[c];
    }
    __syncthreads();
    float acc = pb[tid];
    const float* w = pw + tid * (C_IN * PATCH);
    #pragma unroll
    for (int k = 0; k < C_IN * PATCH; k++) acc = fmaf(p[k], w[k], acc);
    float mean = block_sum_512(acc, sm) * (1.f / D_MODEL);
    float df = acc - mean;
    float var = block_sum_512(df * df, sm) * (1.f / D_MODEL);
    g_h[row * D_MODEL + tid] =
        df * rsqrtf(var + EPS) * lg[tid] + lb[tid] + pos[l * D_MODEL + tid];
}

// ---------------- LayerNorm: fp32 in -> bf16 out -----------------------------
__global__ void k_ln_bf(const float* __restrict__ in, __nv_bfloat16* __restrict__ out,
                        const float* __restrict__ g, const float* __restrict__ b) {
    __shared__ float sm[17];
    int row = blockIdx.x, tid = threadIdx.x;
    float v = in[row * D_MODEL + tid];
    float mean = block_sum_512(v, sm) * (1.f / D_MODEL);
    float df = v - mean;
    float var = block_sum_512(df * df, sm) * (1.f / D_MODEL);
    out[row * D_MODEL + tid] =
        __float2bfloat16(df * rsqrtf(var + EPS) * g[tid] + b[tid]);
}

// ---------------- LayerNorm: fp32 -> fp32 (final) ----------------------------
__global__ void k_ln(const float* __restrict__ in, float* __restrict__ out,
                     const float* __restrict__ g, const float* __restrict__ b) {
    __shared__ float sm[17];
    int row = blockIdx.x, tid = threadIdx.x;
    float v = in[row * D_MODEL + tid];
    float mean = block_sum_512(v, sm) * (1.f / D_MODEL);
    float df = v - mean;
    float var = block_sum_512(df * df, sm) * (1.f / D_MODEL);
    out[row * D_MODEL + tid] = df * rsqrtf(var + EPS) * g[tid] + b[tid];
}

// ---------------- conv + SiLU -> bf16 uc (for x_proj only) -------------------
__global__ void k_conv(const float* __restrict__ cw, const float* __restrict__ cb) {
    int dir = blockIdx.z;
    int idx = blockIdx.x * 256 + threadIdx.x;
    int b = idx >> 10;
    int d = idx & (D_INNER - 1);
    const float* u = g_uz + (size_t)dir * M_ROWS * 2 * D_INNER
                   + (size_t)(b * L_TK) * (2 * D_INNER) + d;
    __nv_bfloat16* o = g_ucb + (size_t)dir * M_ROWS * D_INNER
                     + (size_t)(b * L_TK) * D_INNER + d;
    const float* cwd = cw + (size_t)dir * D_INNER * D_CONV;
    const float* cbd = cb + (size_t)dir * D_INNER;
    float w0 = cwd[d * D_CONV + 0], w1 = cwd[d * D_CONV + 1];
    float w2 = cwd[d * D_CONV + 2], w3 = cwd[d * D_CONV + 3];
    float bias = cbd[d];
    float h0 = 0.f, h1 = 0.f, h2 = 0.f;
    #pragma unroll
    for (int l = 0; l < L_TK; l++) {
        int j = dir ? (15 - l) : l;
        float cur = u[(size_t)j * (2 * D_INNER)];
        float a = bias;
        a = fmaf(w0, h0, a);
        a = fmaf(w1, h1, a);
        a = fmaf(w2, h2, a);
        a = fmaf(w3, cur, a);
        o[(size_t)l * D_INNER] = __float2bfloat16(a / (1.f + __expf(-a)));
        h0 = h1; h1 = h2; h2 = cur;
    }
}

// ------- fused conv-recompute + dt_proj + softplus + scan + gate -------------
__global__ void k_scan(const float* __restrict__ cw,  const float* __restrict__ cb,
                       const float* __restrict__ Wdt, const float* __restrict__ bdt,
                       const float* __restrict__ Alog, const float* __restrict__ Dv) {
    __shared__ ull B2[L_TK][8], C2[L_TK][8];
    __shared__ float dtr[L_TK][DT_RANK];
    int dir = blockIdx.z;
    int b = blockIdx.x;
    int tid = threadIdx.x;
    int d = blockIdx.y * 256 + tid;

    const float* proj = g_proj + (size_t)dir * M_ROWS * PROJW;
    const float* uzp  = g_uz   + (size_t)dir * M_ROWS * 2 * D_INNER;
    const float* cwd  = cw   + (size_t)dir * D_INNER * D_CONV;
    const float* cbd  = cb   + (size_t)dir * D_INNER;
    const float* Wdtd = Wdt  + (size_t)dir * DT_RANK * D_INNER;
    const float* bdtd = bdt  + (size_t)dir * D_INNER;
    const float* Al   = Alog + (size_t)dir * D_INNER * D_STATE;
    const float* Dp   = Dv   + (size_t)dir * D_INNER;

    for (int e = tid; e < L_TK * 8; e += 256) {
        int l = e >> 3, p = e & 7;
        const float* pr = proj + (size_t)(b * L_TK + l) * PROJW;
        float2 vb = *(const float2*)(pr + DT_RANK + p * 2);
        float2 vc = *(const float2*)(pr + DT_RANK + D_STATE + p * 2);
        B2[l][p] = pk2(vb.x, vb.y);
        C2[l][p] = pk2(vc.x, vc.y);
    }
    for (int e = tid; e < L_TK * DT_RANK; e += 256) {
        int l = e >> 5, k = e & 31;
        dtr[l][k] = proj[(size_t)(b * L_TK + l) * PROJW + k];
    }
    __syncthreads();

    // recompute conv + SiLU locally (sliding window over natural rows)
    float ucv[L_TK];
    {
        float w0 = cwd[d * D_CONV + 0], w1 = cwd[d * D_CONV + 1];
        float w2 = cwd[d * D_CONV + 2], w3 = cwd[d * D_CONV + 3];
        float bias = cbd[d];
        float h0 = 0.f, h1 = 0.f, h2 = 0.f;
        #pragma unroll
        for (int l = 0; l < L_TK; l++) {
            int j = dir ? (15 - l) : l;
            float cur = uzp[(size_t)(b * L_TK + j) * (2 * D_INNER) + d];
            float a = bias;
            a = fmaf(w0, h0, a);
            a = fmaf(w1, h1, a);
            a = fmaf(w2, h2, a);
            a = fmaf(w3, cur, a);
            ucv[l] = a / (1.f + __expf(-a));
            h0 = h1; h1 = h2; h2 = cur;
        }
    }

    // dt_proj + softplus (fp32)
    float dtv[L_TK];
    {
        float bias = bdtd[d];
        #pragma unroll
        for (int l = 0; l < L_TK; l++) dtv[l] = bias;
        #pragma unroll 4
        for (int k = 0; k < DT_RANK; k++) {
            float w = Wdtd[(size_t)k * D_INNER + d];
            #pragma unroll
            for (int l = 0; l < L_TK; l++) dtv[l] = fmaf(dtr[l][k], w, dtv[l]);
        }
        #pragma unroll
        for (int l = 0; l < L_TK; l++) dtv[l] = softplusf(dtv[l]);
    }

    float A[D_STATE];
    bool ok = true;
    #pragma unroll
    for (int n = 0; n < D_STATE; n++) {
        A[n] = -__expf(Al[(size_t)d * D_STATE + n]);
        ok = ok && (fabsf(A[n] + (float)(n + 1)) < 2e-3f);
    }
    float Dd = Dp[d];

    if (ok) {
        ull st[8];
        #pragma unroll
        for (int p = 0; p < 8; p++) st[p] = pk2(0.f, 0.f);
        for (int l = 0; l < L_TK; l++) {
            int rn = b * L_TK + (dir ? (15 - l) : l);
            float dt = dtv[l];
            float u  = ucv[l];
            float du = dt * u;
            float q  = __expf(-dt);
            float qq = q * q;
            ull w    = pk2(q, qq);
            ull step = pk2(qq, qq);
            ull du2  = pk2(du, du);
            ull y2   = pk2(0.f, 0.f);
            #pragma unroll
            for (int p = 0; p < 8; p++) {
                st[p] = fma2(st[p], w, mul2(du2, B2[l][p]));
                y2 = fma2(st[p], C2[l][p], y2);
                w = mul2(w, step);
            }
            float ylo, yhi;
            upk2(y2, ylo, yhi);
            float y = ylo + yhi + u * Dd;
            float zv = uzp[(size_t)rn * (2 * D_INNER) + D_INNER + d];
            g_ysb[(size_t)rn * (2 * D_INNER) + dir * D_INNER + d] =
                __float2bfloat16(y * (zv / (1.f + __expf(-zv))));
        }
    } else {
        float st[D_STATE];
        #pragma unroll
        for (int n = 0; n < D_STATE; n++) st[n] = 0.f;
        for (int l = 0; l < L_TK; l++) {
            int rn = b * L_TK + (dir ? (15 - l) : l);
            float dt = dtv[l];
            float u  = ucv[l];
            float du = dt * u;
            float y = 0.f;
            #pragma unroll
            for (int n = 0; n < D_STATE; n++) {
                float blo, bhi, clo, chi;
                upk2(B2[l][n >> 1], blo, bhi);
                upk2(C2[l][n >> 1], clo, chi);
                float Bv = (n & 1) ? bhi : blo;
                float Cv = (n & 1) ? chi : clo;
                float s = fmaf(st[n], __expf(dt * A[n]), du * Bv);
                st[n] = s;
                y = fmaf(s, Cv, y);
            }
            y = fmaf(u, Dd, y);
            float zv = uzp[(size_t)rn * (2 * D_INNER) + D_INNER + d];
            g_ysb[(size_t)rn * (2 * D_INNER) + dir * D_INNER + d] =
                __float2bfloat16(y * (zv / (1.f + __expf(-zv))));
        }
    }
}

// ---------------- launch -----------------------------------------------------
extern "C" void kernel_launch(void* const* d_in, const int* in_sizes, int n_in,
                              void* d_out, int out_size) {
    const float* x    = (const float*)d_in[0];
    const float* bng  = (const float*)d_in[1];
    const float* bnb  = (const float*)d_in[2];
    const float* bnm  = (const float*)d_in[3];
    const float* bnv  = (const float*)d_in[4];
    const float* pw   = (const float*)d_in[5];
    const float* pb   = (const float*)d_in[6];
    const float* lpg  = (const float*)d_in[7];
    const float* lpb  = (const float*)d_in[8];
    const float* pos  = (const float*)d_in[9];
    const float* blg  = (const float*)d_in[10];
    const float* blb  = (const float*)d_in[11];
    const float* Wi   = (const float*)d_in[12];
    const float* cw   = (const float*)d_in[13];
    const float* cb   = (const float*)d_in[14];
    const float* Wx   = (const float*)d_in[15];
    const float* Wdt  = (const float*)d_in[16];
    const float* bdt  = (const float*)d_in[17];
    const float* Alog = (const float*)d_in[18];
    const float* Dv   = (const float*)d_in[19];
    const float* Wo   = (const float*)d_in[20];
    const float* flg  = (const float*)d_in[21];
    const float* flb  = (const float*)d_in[22];
    float* out = (float*)d_out;

    float *ph, *puz, *pproj;
    __nv_bfloat16 *phnb, *pucb, *pysb, *pwib, *pwob, *pwxb;
    cudaGetSymbolAddress((void**)&ph,   g_h);
    cudaGetSymbolAddress((void**)&puz,  g_uz);
    cudaGetSymbolAddress((void**)&pproj,g_proj);
    cudaGetSymbolAddress((void**)&phnb, g_hnb);
    cudaGetSymbolAddress((void**)&pucb, g_ucb);
    cudaGetSymbolAddress((void**)&pysb, g_ysb);
    cudaGetSymbolAddress((void**)&pwib, g_wib);
    cudaGetSymbolAddress((void**)&pwob, g_wob);
    cudaGetSymbolAddress((void**)&pwxb, g_wxb);

    static int attr_done = 0;
    if (!attr_done) {
        cudaFuncSetAttribute(k_mmab<128,128,2,4,0>,
                             cudaFuncAttributeMaxDynamicSharedMemorySize, MMAB_SMEM);
        cudaFuncSetAttribute(k_mmab<128,128,2,4,2>,
                             cudaFuncAttributeMaxDynamicSharedMemorySize, MMAB_SMEM);
        attr_done = 1;
    }

    // weight transpose-convert
    k_tb<<<dim3(2 * D_INNER / 32, D_MODEL / 32, 4), dim3(32, 8)>>>(
        Wi, pwib, D_MODEL, 2 * D_INNER);
    k_tb<<<dim3(D_MODEL / 32, 2 * D_INNER / 32, 2), dim3(32, 8)>>>(
        Wo, pwob, 2 * D_INNER, D_MODEL);
    k_tb<<<dim3(PROJW / 32, D_INNER / 32, 4), dim3(32, 8)>>>(
        Wx, pwxb, D_INNER, PROJW);

    k_patch<<<M_ROWS, 512>>>(x, bng, bnb, bnm, bnv, pw, pb, lpg, lpb, pos);

    for (int i = 0; i < 2; i++) {
        k_ln_bf<<<M_ROWS, 512>>>(ph, phnb, blg + i * D_MODEL, blb + i * D_MODEL);

        // in_proj both dirs: bf16 (4096,512)@(512,2048) -> g_uz[dir]
        k_mmab<128,128,2,4,0>
            <<<dim3(2 * D_INNER / 128, M_ROWS / 128, 2), 256, MMAB_SMEM>>>(
            phnb, D_MODEL, 0,
            pwib + (size_t)i * 2 * 2 * D_INNER * D_MODEL, D_MODEL,
            (long)2 * D_INNER * D_MODEL,
            puz, 2 * D_INNER, (long)M_ROWS * 2 * D_INNER,
            D_MODEL);

        // conv + SiLU both dirs -> bf16 uc
        k_conv<<<dim3((B_SZ * D_INNER) / 256, 1, 2), 256>>>(
            cw + (size_t)i * 2 * D_INNER * D_CONV, cb + (size_t)i * 2 * D_INNER);

        // x_proj both dirs: bf16 (4096,1024)@(1024,64) -> g_proj[dir]
        k_mmab<64,64,2,2,0>
            <<<dim3(1, M_ROWS / 64, 2), 128, XPROJ_SMEM>>>(
            pucb, D_INNER, (long)M_ROWS * D_INNER,
            pwxb + (size_t)i * 2 * PROJW * D_INNER, D_INNER,
            (long)PROJW * D_INNER,
            pproj, PROJW, (long)M_ROWS * PROJW,
            D_INNER);

        // fused conv-recompute + dt_proj + scan both dirs -> g_ysb (bf16)
        k_scan<<<dim3(B_SZ, D_INNER / 256, 2), 256>>>(
            cw   + (size_t)i * 2 * D_INNER * D_CONV,
            cb   + (size_t)i * 2 * D_INNER,
            Wdt  + (size_t)i * 2 * DT_RANK * D_INNER,
            bdt  + (size_t)i * 2 * D_INNER,
            Alog + (size_t)i * 2 * D_INNER * D_STATE,
            Dv   + (size_t)i * 2 * D_INNER);

        // out_proj: bf16 (4096,2048)@(2048,512) += g_h
        k_mmab<128,128,2,4,2>
            <<<dim3(D_MODEL / 128, M_ROWS / 128, 1), 256, MMAB_SMEM>>>(
            pysb, 2 * D_INNER, 0,
            pwob + (size_t)i * 2 * D_INNER * D_MODEL, 2 * D_INNER, 0,
            ph, D_MODEL, 0,
            2 * D_INNER);
    }
    k_ln<<<M_ROWS, 512>>>(ph, out, flg, flb);
}

// round 13
// speedup vs baseline: 1.6451x; 1.6451x over previous
#include <cuda_runtime.h>
#include <cuda_bf16.h>
#include <math.h>
#include <stdint.h>

#define B_SZ   256
#define C_IN   7
#define T_LEN  160
#define PATCH  10
#define L_TK   16
#define D_MODEL 512
#define D_INNER 1024
#define D_STATE 16
#define DT_RANK 32
#define D_CONV  4
#define M_ROWS (B_SZ * L_TK)          // 4096
#define PROJW  (DT_RANK + 2*D_STATE)  // 64
#define KPATCH (C_IN * PATCH)         // 70
#define EPS 1e-5f

// ---------------- scratch ----------------------------------------------------
__device__ float g_h  [M_ROWS * D_MODEL];
__device__ float g_uz [2 * M_ROWS * 2 * D_INNER];
__device__ float g_uc [2 * M_ROWS * D_INNER];
__device__ float g_proj[2 * M_ROWS * PROJW];
__device__ float g_pwt[KPATCH * D_MODEL];                    // transposed patch_w
__device__ __nv_bfloat16 g_hnb[M_ROWS * D_MODEL];
__device__ __nv_bfloat16 g_ysb[M_ROWS * 2 * D_INNER];        // [row][dir*1024+d]
__device__ __nv_bfloat16 g_wib[4 * 2 * D_INNER * D_MODEL];   // 4 x [2048][512]
__device__ __nv_bfloat16 g_wob[2 * 2 * D_INNER * D_MODEL];   // 2 x [512][2048]

// ---------------- helpers ----------------------------------------------------
__device__ __forceinline__ uint32_t f2tf(float x) {
    uint32_t r; asm("cvt.rna.tf32.f32 %0, %1;" : "=r"(r) : "f"(x)); return r;
}
__device__ __forceinline__ void mma8(float* c, const uint32_t* a, const uint32_t* b) {
    asm volatile(
        "mma.sync.aligned.m16n8k8.row.col.f32.tf32.tf32.f32 "
        "{%0,%1,%2,%3},{%4,%5,%6,%7},{%8,%9},{%0,%1,%2,%3};"
        : "+f"(c[0]), "+f"(c[1]), "+f"(c[2]), "+f"(c[3])
        : "r"(a[0]), "r"(a[1]), "r"(a[2]), "r"(a[3]), "r"(b[0]), "r"(b[1]));
}
__device__ __forceinline__ void mma16(float* c, const uint32_t* a, const uint32_t* b) {
    asm volatile(
        "mma.sync.aligned.m16n8k16.row.col.f32.bf16.bf16.f32 "
        "{%0,%1,%2,%3},{%4,%5,%6,%7},{%8,%9},{%0,%1,%2,%3};"
        : "+f"(c[0]), "+f"(c[1]), "+f"(c[2]), "+f"(c[3])
        : "r"(a[0]), "r"(a[1]), "r"(a[2]), "r"(a[3]), "r"(b[0]), "r"(b[1]));
}
__device__ __forceinline__ void ldsm4(uint32_t& r0, uint32_t& r1, uint32_t& r2,
                                      uint32_t& r3, uint32_t addr) {
    asm volatile("ldmatrix.sync.aligned.m8n8.x4.shared.b16 {%0,%1,%2,%3}, [%4];"
                 : "=r"(r0), "=r"(r1), "=r"(r2), "=r"(r3) : "r"(addr));
}
__device__ __forceinline__ float softplusf(float v) {
    return fmaxf(v, 0.f) + log1pf(__expf(-fabsf(v)));
}
__device__ __forceinline__ void cp16(void* dst, const void* src) {
    uint32_t d = (uint32_t)__cvta_generic_to_shared(dst);
    asm volatile("cp.async.cg.shared.global [%0], [%1], 16;" :: "r"(d), "l"(src));
}
#define CP_COMMIT() asm volatile("cp.async.commit_group;")
#define CP_WAIT1()  asm volatile("cp.async.wait_group 1;")
#define CP_WAIT2()  asm volatile("cp.async.wait_group 2;")

typedef unsigned long long ull;
__device__ __forceinline__ ull pk2(float x, float y) {
    ull r; asm("mov.b64 %0, {%1,%2};" : "=l"(r) : "f"(x), "f"(y)); return r;
}
__device__ __forceinline__ void upk2(ull v, float& x, float& y) {
    asm("mov.b64 {%0,%1}, %2;" : "=f"(x), "=f"(y) : "l"(v));
}
__device__ __forceinline__ ull fma2(ull a, ull b, ull c) {
    ull d; asm("fma.rn.f32x2 %0, %1, %2, %3;" : "=l"(d) : "l"(a), "l"(b), "l"(c)); return d;
}
__device__ __forceinline__ ull mul2(ull a, ull b) {
    ull d; asm("mul.rn.f32x2 %0, %1, %2;" : "=l"(d) : "l"(a), "l"(b)); return d;
}

__device__ __forceinline__ float block_sum_512(float v, float* sm) {
    int tid = threadIdx.x;
    #pragma unroll
    for (int o = 16; o; o >>= 1) v += __shfl_xor_sync(0xffffffffu, v, o);
    if ((tid & 31) == 0) sm[tid >> 5] = v;
    __syncthreads();
    if (tid == 0) {
        float s = 0.f;
        #pragma unroll
        for (int i = 0; i < 16; i++) s += sm[i];
        sm[16] = s;
    }
    __syncthreads();
    float r = sm[16];
    __syncthreads();
    return r;
}

// ---------------- transpose + convert weights to bf16 ------------------------
__global__ void k_tb(const float* __restrict__ src, __nv_bfloat16* __restrict__ dst,
                     int K, int N) {
    __shared__ __nv_bfloat16 t[32][33];
    long zo = (long)blockIdx.z * K * N;
    int n0 = blockIdx.x * 32, k0 = blockIdx.y * 32;
    for (int i = threadIdx.y; i < 32; i += 8)
        t[i][threadIdx.x] = __float2bfloat16(src[zo + (size_t)(k0 + i) * N + n0 + threadIdx.x]);
    __syncthreads();
    for (int i = threadIdx.y; i < 32; i += 8)
        dst[zo + (size_t)(n0 + i) * K + k0 + threadIdx.x] = t[threadIdx.x][i];
}

// ---------------- transpose patch_w [512][70] -> [70][512] -------------------
__global__ void k_tpw(const float* __restrict__ src, float* __restrict__ dst) {
    int k = blockIdx.x;                // 0..69
    int n = threadIdx.x;               // 0..511
    dst[k * D_MODEL + n] = src[(size_t)n * KPATCH + k];
}

// ---------------- 3-stage bf16 MMA GEMM with ldmatrix ------------------------
// A [M][K] bf16 row-major, B [N][K] bf16 row-major (pre-transposed weights).
// EPI: 0 = store fp32, 2 = accumulate fp32. Dynamic smem (3 stages).
template<int BM, int BN, int WARPS_M, int WARPS_N, int EPI>
__global__ void __launch_bounds__(WARPS_M * WARPS_N * 32)
k_mmab(const __nv_bfloat16* __restrict__ A, int lda, long strideAz,
       const __nv_bfloat16* __restrict__ Bg, int ldb, long strideBz,
       float* __restrict__ C, int ldc, long strideCz, int K) {
    constexpr int BK = 32;
    constexpr int LDP = 20;               // 80B row stride: 16B aligned, conflict-free
    constexpr int NS  = 3;
    constexpr int T  = WARPS_M * WARPS_N * 32;
    constexpr int WTM = BM / WARPS_M;
    constexpr int WTN = BN / WARPS_N;
    constexpr int MT  = WTM / 16;
    constexpr int NT  = WTN / 8;
    static_assert(NT % 2 == 0, "NT must be even for paired B ldmatrix");

    extern __shared__ uint32_t dyn[];
    typedef uint32_t ATile[BM][LDP];
    typedef uint32_t BTile[BN][LDP];
    ATile* As2 = (ATile*)dyn;
    BTile* Bs2 = (BTile*)(dyn + NS * BM * LDP);

    int tid = threadIdx.x, lane = tid & 31, wid = tid >> 5;
    int wm = wid % WARPS_M, wn = wid / WARPS_M;
    int m0 = blockIdx.y * BM, n0 = blockIdx.x * BN;
    int z = blockIdx.z;
    int tig = lane & 3, grp = lane >> 2;

    const __nv_bfloat16* Ap = A + (long)z * strideAz;
    const __nv_bfloat16* Bp = Bg + (long)z * strideBz;
    float* Cp = C + (long)z * strideCz;

    int a_row_off = (lane & 7) + ((lane >> 3) & 1) * 8;
    int a_col_off = ((lane >> 4) & 1) * 4;
    int b_row_off = (lane & 7) + ((lane >> 4) & 1) * 8;
    int b_col_off = ((lane >> 3) & 1) * 4;

    float acc[MT][NT][4];
    #pragma unroll
    for (int i = 0; i < MT; i++)
        #pragma unroll
        for (int j = 0; j < NT; j++)
            #pragma unroll
            for (int q = 0; q < 4; q++) acc[i][j][q] = 0.f;

    auto load_tiles = [&](int st, int k0) {
        #pragma unroll 2
        for (int idx = tid; idx < BM * 4; idx += T) {
            int m = idx >> 2, c = idx & 3;
            cp16(&As2[st][m][c * 4], Ap + (size_t)(m0 + m) * lda + k0 + c * 8);
        }
        #pragma unroll 2
        for (int idx = tid; idx < BN * 4; idx += T) {
            int n = idx >> 2, c = idx & 3;
            cp16(&Bs2[st][n][c * 4], Bp + (size_t)(n0 + n) * ldb + k0 + c * 8);
        }
    };

    int KT = K / BK;
    load_tiles(0, 0);
    CP_COMMIT();
    load_tiles(1, BK);
    CP_COMMIT();
    int st = 0;
    for (int kt = 0; kt < KT; kt++) {
        if (kt + 2 < KT) {
            int s2 = st + 2; if (s2 >= NS) s2 -= NS;
            load_tiles(s2, (kt + 2) * BK);
        }
        CP_COMMIT();
        CP_WAIT2();
        __syncthreads();

        uint32_t aBase = (uint32_t)__cvta_generic_to_shared(&As2[st][0][0]);
        uint32_t bBase = (uint32_t)__cvta_generic_to_shared(&Bs2[st][0][0]);
        #pragma unroll
        for (int ks = 0; ks < 2; ks++) {
            int pb = ks * 8;
            uint32_t afr[MT][4], bfr[NT][2];
            #pragma unroll
            for (int i = 0; i < MT; i++) {
                int r = wm * WTM + i * 16;
                uint32_t addr = aBase +
                    (uint32_t)(((r + a_row_off) * LDP + pb + a_col_off) * 4);
                ldsm4(afr[i][0], afr[i][1], afr[i][2], afr[i][3], addr);
            }
            #pragma unroll
            for (int j = 0; j < NT; j += 2) {
                int nb = wn * WTN + j * 8;
                uint32_t addr = bBase +
                    (uint32_t)(((nb + b_row_off) * LDP + pb + b_col_off) * 4);
                ldsm4(bfr[j][0], bfr[j][1], bfr[j + 1][0], bfr[j + 1][1], addr);
            }
            #pragma unroll
            for (int i = 0; i < MT; i++)
                #pragma unroll
                for (int j = 0; j < NT; j++)
                    mma16(acc[i][j], afr[i], bfr[j]);
        }
        __syncthreads();
        if (++st >= NS) st = 0;
    }

    #pragma unroll
    for (int i = 0; i < MT; i++) {
        #pragma unroll
        for (int half = 0; half < 2; half++) {
            int r = m0 + wm * WTM + i * 16 + grp + half * 8;
            #pragma unroll
            for (int j = 0; j < NT; j++) {
                int n = n0 + wn * WTN + j * 8 + tig * 2;
                float v0 = acc[i][j][half * 2 + 0];
                float v1 = acc[i][j][half * 2 + 1];
                float* cp = Cp + (size_t)r * ldc + n;
                if (EPI == 2) {
                    cp[0] += v0;
                    cp[1] += v1;
                } else {
                    *(float2*)cp = make_float2(v0, v1);
                }
            }
        }
    }
}
#define MMAB_SMEM (3 * (128 * 20 + 128 * 20) * 4)

// ---------------- tf32 MMA GEMM (x_proj) -------------------------------------
template<int BM, int BN, int WARPS_M, int WARPS_N>
__global__ void __launch_bounds__(WARPS_M * WARPS_N * 32)
k_mma(const float* __restrict__ A, int lda, long strideAz,
      const float* __restrict__ Bg, int ldb, long strideBz,
      float* __restrict__ C, int ldc, long strideCz, int K) {
    constexpr int BK = 16;
    constexpr int T  = WARPS_M * WARPS_N * 32;
    constexpr int WTM = BM / WARPS_M;
    constexpr int WTN = BN / WARPS_N;
    constexpr int MT  = WTM / 16;
    constexpr int NT  = WTN / 8;

    __shared__ float As[2][BM][BK + 4];
    __shared__ float Bs[2][BK][BN + 8];

    int tid = threadIdx.x, lane = tid & 31, wid = tid >> 5;
    int wm = wid % WARPS_M, wn = wid / WARPS_M;
    int m0 = blockIdx.y * BM, n0 = blockIdx.x * BN;
    int z = blockIdx.z;
    int tig = lane & 3, grp = lane >> 2;

    const float* Ap = A + (long)z * strideAz;
    const float* Bp = Bg + (long)z * strideBz;
    float* Cp = C + (long)z * strideCz;

    float acc[MT][NT][4];
    #pragma unroll
    for (int i = 0; i < MT; i++)
        #pragma unroll
        for (int j = 0; j < NT; j++)
            #pragma unroll
            for (int q = 0; q < 4; q++) acc[i][j][q] = 0.f;

    auto load_tiles = [&](int st, int k0) {
        #pragma unroll 2
        for (int idx = tid; idx < BM * 4; idx += T) {
            int m = idx >> 2, kq = idx & 3;
            cp16(&As[st][m][kq * 4], Ap + (size_t)(m0 + m) * lda + k0 + kq * 4);
        }
        #pragma unroll 2
        for (int idx = tid; idx < BK * BN / 4; idx += T) {
            int k = idx / (BN / 4), nq = idx % (BN / 4);
            cp16(&Bs[st][k][nq * 4], Bp + (size_t)(k0 + k) * ldb + n0 + nq * 4);
        }
    };

    int KT = K / BK;
    load_tiles(0, 0);
    CP_COMMIT();
    for (int kt = 0; kt < KT; kt++) {
        if (kt + 1 < KT) load_tiles((kt + 1) & 1, (kt + 1) * BK);
        CP_COMMIT();
        CP_WAIT1();
        __syncthreads();
        int st = kt & 1;
        #pragma unroll
        for (int ks = 0; ks < 2; ks++) {
            int c = ks * 8 + tig;
            uint32_t afr[MT][4], bfr[NT][2];
            #pragma unroll
            for (int i = 0; i < MT; i++) {
                int r = wm * WTM + i * 16 + grp;
                afr[i][0] = f2tf(As[st][r][c]);
                afr[i][1] = f2tf(As[st][r + 8][c]);
                afr[i][2] = f2tf(As[st][r][c + 4]);
                afr[i][3] = f2tf(As[st][r + 8][c + 4]);
            }
            #pragma unroll
            for (int j = 0; j < NT; j++) {
                int nb = wn * WTN + j * 8 + grp;
                bfr[j][0] = f2tf(Bs[st][c][nb]);
                bfr[j][1] = f2tf(Bs[st][c + 4][nb]);
            }
            #pragma unroll
            for (int i = 0; i < MT; i++)
                #pragma unroll
                for (int j = 0; j < NT; j++)
                    mma8(acc[i][j], afr[i], bfr[j]);
        }
        __syncthreads();
    }

    #pragma unroll
    for (int i = 0; i < MT; i++) {
        #pragma unroll
        for (int half = 0; half < 2; half++) {
            int r = m0 + wm * WTM + i * 16 + grp + half * 8;
            #pragma unroll
            for (int j = 0; j < NT; j++) {
                int n = n0 + wn * WTN + j * 8 + tig * 2;
                *(float2*)(Cp + (size_t)r * ldc + n) =
                    make_float2(acc[i][j][half * 2 + 0], acc[i][j][half * 2 + 1]);
            }
        }
    }
}

// ---------------- patch embed + LN + pos (coalesced pwT) ---------------------
__global__ void k_patch(const float* __restrict__ x,
                        const float* __restrict__ bng, const float* __restrict__ bnb,
                        const float* __restrict__ bnm, const float* __restrict__ bnv,
                        const float* __restrict__ pb,
                        const float* __restrict__ lg,  const float* __restrict__ lb,
                        const float* __restrict__ pos) {
    __shared__ float p[KPATCH];
    __shared__ float sm[17];
    int row = blockIdx.x, tid = threadIdx.x;
    int b = row >> 4, l = row & 15;
    if (tid < KPATCH) {
        int c = tid / PATCH, j = tid - c * PATCH;
        float xv = x[(b * C_IN + c) * T_LEN + l * PATCH + j];
        p[tid] = (xv - bnm[c]) * rsqrtf(bnv[c] + EPS) * bng[c] + bnb[c];
    }
    __syncthreads();
    float acc = pb[tid];
    const float* wt = g_pwt + tid;            // coalesced: pwT[k*512 + tid]
    #pragma unroll 7
    for (int k = 0; k < KPATCH; k++)
        acc = fmaf(p[k], wt[(size_t)k * D_MODEL], acc);
    float mean = block_sum_512(acc, sm) * (1.f / D_MODEL);
    float df = acc - mean;
    float var = block_sum_512(df * df, sm) * (1.f / D_MODEL);
    g_h[row * D_MODEL + tid] =
        df * rsqrtf(var + EPS) * lg[tid] + lb[tid] + pos[l * D_MODEL + tid];
}

// ---------------- LayerNorm: fp32 in -> bf16 out -----------------------------
__global__ void k_ln_bf(const float* __restrict__ in, __nv_bfloat16* __restrict__ out,
                        const float* __restrict__ g, const float* __restrict__ b) {
    __shared__ float sm[17];
    int row = blockIdx.x, tid = threadIdx.x;
    float v = in[row * D_MODEL + tid];
    float mean = block_sum_512(v, sm) * (1.f / D_MODEL);
    float df = v - mean;
    float var = block_sum_512(df * df, sm) * (1.f / D_MODEL);
    out[row * D_MODEL + tid] =
        __float2bfloat16(df * rsqrtf(var + EPS) * g[tid] + b[tid]);
}

// ---------------- LayerNorm: fp32 -> fp32 (final) ----------------------------
__global__ void k_ln(const float* __restrict__ in, float* __restrict__ out,
                     const float* __restrict__ g, const float* __restrict__ b) {
    __shared__ float sm[17];
    int row = blockIdx.x, tid = threadIdx.x;
    float v = in[row * D_MODEL + tid];
    float mean = block_sum_512(v, sm) * (1.f / D_MODEL);
    float df = v - mean;
    float var = block_sum_512(df * df, sm) * (1.f / D_MODEL);
    out[row * D_MODEL + tid] = df * rsqrtf(var + EPS) * g[tid] + b[tid];
}

// ---------------- causal depthwise conv + SiLU, both dirs -------------------
__global__ void k_conv(const float* __restrict__ cw, const float* __restrict__ cb) {
    int dir = blockIdx.z;
    int idx = blockIdx.x * 256 + threadIdx.x;
    int b = idx >> 10;
    int d = idx & (D_INNER - 1);
    const float* u = g_uz + (size_t)dir * M_ROWS * 2 * D_INNER
                   + (size_t)(b * L_TK) * (2 * D_INNER) + d;
    float* o = g_uc + (size_t)dir * M_ROWS * D_INNER
             + (size_t)(b * L_TK) * D_INNER + d;
    const float* cwd = cw + (size_t)dir * D_INNER * D_CONV;
    const float* cbd = cb + (size_t)dir * D_INNER;
    float w0 = cwd[d * D_CONV + 0], w1 = cwd[d * D_CONV + 1];
    float w2 = cwd[d * D_CONV + 2], w3 = cwd[d * D_CONV + 3];
    float bias = cbd[d];
    float h0 = 0.f, h1 = 0.f, h2 = 0.f;
    #pragma unroll
    for (int l = 0; l < L_TK; l++) {
        int j = dir ? (15 - l) : l;
        float cur = u[(size_t)j * (2 * D_INNER)];
        float a = bias;
        a = fmaf(w0, h0, a);
        a = fmaf(w1, h1, a);
        a = fmaf(w2, h2, a);
        a = fmaf(w3, cur, a);
        o[(size_t)l * D_INNER] = a / (1.f + __expf(-a));
        h0 = h1; h1 = h2; h2 = cur;
    }
}

// ---------------- fused dt_proj + softplus + scan + D skip + gate ------------
__global__ void k_scan(const float* __restrict__ Wdt, const float* __restrict__ bdt,
                       const float* __restrict__ Alog, const float* __restrict__ Dv) {
    __shared__ ull B2[L_TK][8], C2[L_TK][8];
    __shared__ float dtr[L_TK][DT_RANK];
    int dir = blockIdx.z;
    int b = blockIdx.x;
    int tid = threadIdx.x;
    int d = blockIdx.y * 256 + tid;

    const float* proj = g_proj + (size_t)dir * M_ROWS * PROJW;
    const float* ucp  = g_uc   + (size_t)dir * M_ROWS * D_INNER;
    const float* uzp  = g_uz   + (size_t)dir * M_ROWS * 2 * D_INNER;
    const float* Wdtd = Wdt  + (size_t)dir * DT_RANK * D_INNER;
    const float* bdtd = bdt  + (size_t)dir * D_INNER;
    const float* Al   = Alog + (size_t)dir * D_INNER * D_STATE;
    const float* Dp   = Dv   + (size_t)dir * D_INNER;

    for (int e = tid; e < L_TK * 8; e += 256) {
        int l = e >> 3, p = e & 7;
        const float* pr = proj + (size_t)(b * L_TK + l) * PROJW;
        float2 vb = *(const float2*)(pr + DT_RANK + p * 2);
        float2 vc = *(const float2*)(pr + DT_RANK + D_STATE + p * 2);
        B2[l][p] = pk2(vb.x, vb.y);
        C2[l][p] = pk2(vc.x, vc.y);
    }
    for (int e = tid; e < L_TK * DT_RANK; e += 256) {
        int l = e >> 5, k = e & 31;
        dtr[l][k] = proj[(size_t)(b * L_TK + l) * PROJW + k];
    }
    __syncthreads();

    float dtv[L_TK];
    {
        float bias = bdtd[d];
        #pragma unroll
        for (int l = 0; l < L_TK; l++) dtv[l] = bias;
        #pragma unroll 4
        for (int k = 0; k < DT_RANK; k++) {
            float w = Wdtd[(size_t)k * D_INNER + d];
            #pragma unroll
            for (int l = 0; l < L_TK; l++) dtv[l] = fmaf(dtr[l][k], w, dtv[l]);
        }
        #pragma unroll
        for (int l = 0; l < L_TK; l++) dtv[l] = softplusf(dtv[l]);
    }

    float A[D_STATE];
    bool ok = true;
    #pragma unroll
    for (int n = 0; n < D_STATE; n++) {
        A[n] = -__expf(Al[(size_t)d * D_STATE + n]);
        ok = ok && (fabsf(A[n] + (float)(n + 1)) < 2e-3f);
    }
    float Dd = Dp[d];

    if (ok) {
        ull st[8];
        #pragma unroll
        for (int p = 0; p < 8; p++) st[p] = pk2(0.f, 0.f);
        for (int l = 0; l < L_TK; l++) {
            int rp = b * L_TK + l;
            int rn = b * L_TK + (dir ? (15 - l) : l);
            float dt = dtv[l];
            float u  = ucp[(size_t)rp * D_INNER + d];
            float du = dt * u;
            float q  = __expf(-dt);
            float qq = q * q;
            ull w    = pk2(q, qq);
            ull step = pk2(qq, qq);
            ull du2  = pk2(du, du);
            ull y2   = pk2(0.f, 0.f);
            #pragma unroll
            for (int p = 0; p < 8; p++) {
                st[p] = fma2(st[p], w, mul2(du2, B2[l][p]));
                y2 = fma2(st[p], C2[l][p], y2);
                w = mul2(w, step);
            }
            float ylo, yhi;
            upk2(y2, ylo, yhi);
            float y = ylo + yhi + u * Dd;
            float zv = uzp[(size_t)rn * (2 * D_INNER) + D_INNER + d];
            g_ysb[(size_t)rn * (2 * D_INNER) + dir * D_INNER + d] =
                __float2bfloat16(y * (zv / (1.f + __expf(-zv))));
        }
    } else {
        float st[D_STATE];
        #pragma unroll
        for (int n = 0; n < D_STATE; n++) st[n] = 0.f;
        for (int l = 0; l < L_TK; l++) {
            int rp = b * L_TK + l;
            int rn = b * L_TK + (dir ? (15 - l) : l);
            float dt = dtv[l];
            float u  = ucp[(size_t)rp * D_INNER + d];
            float du = dt * u;
            float y = 0.f;
            #pragma unroll
            for (int n = 0; n < D_STATE; n++) {
                float blo, bhi, clo, chi;
                upk2(B2[l][n >> 1], blo, bhi);
                upk2(C2[l][n >> 1], clo, chi);
                float Bv = (n & 1) ? bhi : blo;
                float Cv = (n & 1) ? chi : clo;
                float s = fmaf(st[n], __expf(dt * A[n]), du * Bv);
                st[n] = s;
                y = fmaf(s, Cv, y);
            }
            y = fmaf(u, Dd, y);
            float zv = uzp[(size_t)rn * (2 * D_INNER) + D_INNER + d];
            g_ysb[(size_t)rn * (2 * D_INNER) + dir * D_INNER + d] =
                __float2bfloat16(y * (zv / (1.f + __expf(-zv))));
        }
    }
}

// ---------------- launch -----------------------------------------------------
extern "C" void kernel_launch(void* const* d_in, const int* in_sizes, int n_in,
                              void* d_out, int out_size) {
    const float* x    = (const float*)d_in[0];
    const float* bng  = (const float*)d_in[1];
    const float* bnb  = (const float*)d_in[2];
    const float* bnm  = (const float*)d_in[3];
    const float* bnv  = (const float*)d_in[4];
    const float* pw   = (const float*)d_in[5];
    const float* pb   = (const float*)d_in[6];
    const float* lpg  = (const float*)d_in[7];
    const float* lpb  = (const float*)d_in[8];
    const float* pos  = (const float*)d_in[9];
    const float* blg  = (const float*)d_in[10];
    const float* blb  = (const float*)d_in[11];
    const float* Wi   = (const float*)d_in[12];
    const float* cw   = (const float*)d_in[13];
    const float* cb   = (const float*)d_in[14];
    const float* Wx   = (const float*)d_in[15];
    const float* Wdt  = (const float*)d_in[16];
    const float* bdt  = (const float*)d_in[17];
    const float* Alog = (const float*)d_in[18];
    const float* Dv   = (const float*)d_in[19];
    const float* Wo   = (const float*)d_in[20];
    const float* flg  = (const float*)d_in[21];
    const float* flb  = (const float*)d_in[22];
    float* out = (float*)d_out;

    float *ph, *puz, *puc, *pproj, *ppwt;
    __nv_bfloat16 *phnb, *pysb, *pwib, *pwob;
    cudaGetSymbolAddress((void**)&ph,   g_h);
    cudaGetSymbolAddress((void**)&puz,  g_uz);
    cudaGetSymbolAddress((void**)&puc,  g_uc);
    cudaGetSymbolAddress((void**)&pproj,g_proj);
    cudaGetSymbolAddress((void**)&ppwt, g_pwt);
    cudaGetSymbolAddress((void**)&phnb, g_hnb);
    cudaGetSymbolAddress((void**)&pysb, g_ysb);
    cudaGetSymbolAddress((void**)&pwib, g_wib);
    cudaGetSymbolAddress((void**)&pwob, g_wob);

    static int attr_done = 0;
    if (!attr_done) {
        cudaFuncSetAttribute(k_mmab<128,128,2,4,0>,
                             cudaFuncAttributeMaxDynamicSharedMemorySize, MMAB_SMEM);
        cudaFuncSetAttribute(k_mmab<128,128,2,4,2>,
                             cudaFuncAttributeMaxDynamicSharedMemorySize, MMAB_SMEM);
        attr_done = 1;
    }

    // weight transpose-convert
    k_tb<<<dim3(2 * D_INNER / 32, D_MODEL / 32, 4), dim3(32, 8)>>>(
        Wi, pwib, D_MODEL, 2 * D_INNER);
    k_tb<<<dim3(D_MODEL / 32, 2 * D_INNER / 32, 2), dim3(32, 8)>>>(
        Wo, pwob, 2 * D_INNER, D_MODEL);
    k_tpw<<<KPATCH, D_MODEL>>>(pw, ppwt);

    k_patch<<<M_ROWS, 512>>>(x, bng, bnb, bnm, bnv, pb, lpg, lpb, pos);

    for (int i = 0; i < 2; i++) {
        k_ln_bf<<<M_ROWS, 512>>>(ph, phnb, blg + i * D_MODEL, blb + i * D_MODEL);

        // in_proj both dirs: bf16 (4096,512)@(512,2048) -> g_uz[dir]
        k_mmab<128,128,2,4,0>
            <<<dim3(2 * D_INNER / 128, M_ROWS / 128, 2), 256, MMAB_SMEM>>>(
            phnb, D_MODEL, 0,
            pwib + (size_t)i * 2 * 2 * D_INNER * D_MODEL, D_MODEL,
            (long)2 * D_INNER * D_MODEL,
            puz, 2 * D_INNER, (long)M_ROWS * 2 * D_INNER,
            D_MODEL);

        // conv + SiLU both dirs
        k_conv<<<dim3((B_SZ * D_INNER) / 256, 1, 2), 256>>>(
            cw + (size_t)i * 2 * D_INNER * D_CONV, cb + (size_t)i * 2 * D_INNER);

        // x_proj both dirs: tf32 (4096,1024)@(1024,64) -> g_proj[dir]
        k_mma<64,64,2,2><<<dim3(1, M_ROWS / 64, 2), 128>>>(
            puc, D_INNER, (long)M_ROWS * D_INNER,
            Wx + (size_t)i * 2 * D_INNER * PROJW, PROJW, (long)D_INNER * PROJW,
            pproj, PROJW, (long)M_ROWS * PROJW,
            D_INNER);

        // fused dt_proj + scan both dirs -> g_ysb (bf16)
        k_scan<<<dim3(B_SZ, D_INNER / 256, 2), 256>>>(
            Wdt  + (size_t)i * 2 * DT_RANK * D_INNER,
            bdt  + (size_t)i * 2 * D_INNER,
            Alog + (size_t)i * 2 * D_INNER * D_STATE,
            Dv   + (size_t)i * 2 * D_INNER);

        // out_proj: bf16 (4096,2048)@(2048,512) += g_h
        k_mmab<128,128,2,4,2>
            <<<dim3(D_MODEL / 128, M_ROWS / 128, 1), 256, MMAB_SMEM>>>(
            pysb, 2 * D_INNER, 0,
            pwob + (size_t)i * 2 * D_INNER * D_MODEL, 2 * D_INNER, 0,
            ph, D_MODEL, 0,
            2 * D_INNER);
    }
    k_ln<<<M_ROWS, 512>>>(ph, out, flg, flb);
}

// round 14
// speedup vs baseline: 1.6956x; 1.0307x over previous
#include <cuda_runtime.h>
#include <cuda_bf16.h>
#include <math.h>
#include <stdint.h>

#define B_SZ   256
#define C_IN   7
#define T_LEN  160
#define PATCH  10
#define L_TK   16
#define D_MODEL 512
#define D_INNER 1024
#define D_STATE 16
#define DT_RANK 32
#define D_CONV  4
#define M_ROWS (B_SZ * L_TK)          // 4096
#define PROJW  (DT_RANK + 2*D_STATE)  // 64
#define KPATCH (C_IN * PATCH)         // 70
#define PGROW  8                      // rows per patch CTA
#define EPS 1e-5f

// ---------------- scratch ----------------------------------------------------
__device__ float g_h  [M_ROWS * D_MODEL];
__device__ float g_uz [2 * M_ROWS * 2 * D_INNER];
__device__ float g_uc [2 * M_ROWS * D_INNER];
__device__ float g_proj[2 * M_ROWS * PROJW];
__device__ float g_pwt[KPATCH * D_MODEL];                    // transposed patch_w
__device__ __nv_bfloat16 g_hnb[M_ROWS * D_MODEL];
__device__ __nv_bfloat16 g_ysb[M_ROWS * 2 * D_INNER];        // [row][dir*1024+d]
__device__ __nv_bfloat16 g_wib[4 * 2 * D_INNER * D_MODEL];   // 4 x [2048][512]
__device__ __nv_bfloat16 g_wob[2 * 2 * D_INNER * D_MODEL];   // 2 x [512][2048]

// ---------------- helpers ----------------------------------------------------
__device__ __forceinline__ uint32_t f2tf(float x) {
    uint32_t r; asm("cvt.rna.tf32.f32 %0, %1;" : "=r"(r) : "f"(x)); return r;
}
__device__ __forceinline__ void mma8(float* c, const uint32_t* a, const uint32_t* b) {
    asm volatile(
        "mma.sync.aligned.m16n8k8.row.col.f32.tf32.tf32.f32 "
        "{%0,%1,%2,%3},{%4,%5,%6,%7},{%8,%9},{%0,%1,%2,%3};"
        : "+f"(c[0]), "+f"(c[1]), "+f"(c[2]), "+f"(c[3])
        : "r"(a[0]), "r"(a[1]), "r"(a[2]), "r"(a[3]), "r"(b[0]), "r"(b[1]));
}
__device__ __forceinline__ void mma16(float* c, const uint32_t* a, const uint32_t* b) {
    asm volatile(
        "mma.sync.aligned.m16n8k16.row.col.f32.bf16.bf16.f32 "
        "{%0,%1,%2,%3},{%4,%5,%6,%7},{%8,%9},{%0,%1,%2,%3};"
        : "+f"(c[0]), "+f"(c[1]), "+f"(c[2]), "+f"(c[3])
        : "r"(a[0]), "r"(a[1]), "r"(a[2]), "r"(a[3]), "r"(b[0]), "r"(b[1]));
}
__device__ __forceinline__ void ldsm4(uint32_t& r0, uint32_t& r1, uint32_t& r2,
                                      uint32_t& r3, uint32_t addr) {
    asm volatile("ldmatrix.sync.aligned.m8n8.x4.shared.b16 {%0,%1,%2,%3}, [%4];"
                 : "=r"(r0), "=r"(r1), "=r"(r2), "=r"(r3) : "r"(addr));
}
__device__ __forceinline__ float softplusf(float v) {
    return fmaxf(v, 0.f) + log1pf(__expf(-fabsf(v)));
}
__device__ __forceinline__ void cp16(void* dst, const void* src) {
    uint32_t d = (uint32_t)__cvta_generic_to_shared(dst);
    asm volatile("cp.async.cg.shared.global [%0], [%1], 16;" :: "r"(d), "l"(src));
}
#define CP_COMMIT() asm volatile("cp.async.commit_group;")
#define CP_WAIT1()  asm volatile("cp.async.wait_group 1;")
#define CP_WAIT2()  asm volatile("cp.async.wait_group 2;")

typedef unsigned long long ull;
__device__ __forceinline__ ull pk2(float x, float y) {
    ull r; asm("mov.b64 %0, {%1,%2};" : "=l"(r) : "f"(x), "f"(y)); return r;
}
__device__ __forceinline__ void upk2(ull v, float& x, float& y) {
    asm("mov.b64 {%0,%1}, %2;" : "=f"(x), "=f"(y) : "l"(v));
}
__device__ __forceinline__ ull fma2(ull a, ull b, ull c) {
    ull d; asm("fma.rn.f32x2 %0, %1, %2, %3;" : "=l"(d) : "l"(a), "l"(b), "l"(c)); return d;
}
__device__ __forceinline__ ull mul2(ull a, ull b) {
    ull d; asm("mul.rn.f32x2 %0, %1, %2;" : "=l"(d) : "l"(a), "l"(b)); return d;
}

__device__ __forceinline__ float block_sum_512(float v, float* sm) {
    int tid = threadIdx.x;
    #pragma unroll
    for (int o = 16; o; o >>= 1) v += __shfl_xor_sync(0xffffffffu, v, o);
    if ((tid & 31) == 0) sm[tid >> 5] = v;
    __syncthreads();
    if (tid == 0) {
        float s = 0.f;
        #pragma unroll
        for (int i = 0; i < 16; i++) s += sm[i];
        sm[16] = s;
    }
    __syncthreads();
    float r = sm[16];
    __syncthreads();
    return r;
}

// ---------------- transpose + convert weights to bf16 ------------------------
__global__ void k_tb(const float* __restrict__ src, __nv_bfloat16* __restrict__ dst,
                     int K, int N) {
    __shared__ __nv_bfloat16 t[32][33];
    long zo = (long)blockIdx.z * K * N;
    int n0 = blockIdx.x * 32, k0 = blockIdx.y * 32;
    for (int i = threadIdx.y; i < 32; i += 8)
        t[i][threadIdx.x] = __float2bfloat16(src[zo + (size_t)(k0 + i) * N + n0 + threadIdx.x]);
    __syncthreads();
    for (int i = threadIdx.y; i < 32; i += 8)
        dst[zo + (size_t)(n0 + i) * K + k0 + threadIdx.x] = t[threadIdx.x][i];
}

// ---------------- transpose patch_w [512][70] -> [70][512] -------------------
__global__ void k_tpw(const float* __restrict__ src, float* __restrict__ dst) {
    int k = blockIdx.x;                // 0..69
    int n = threadIdx.x;               // 0..511
    dst[k * D_MODEL + n] = src[(size_t)n * KPATCH + k];
}

// ---------------- 3-stage bf16 MMA GEMM with ldmatrix ------------------------
// A [M][K] bf16 row-major, B [N][K] bf16 row-major (pre-transposed weights).
// EPI: 0 = store fp32, 2 = accumulate fp32. Dynamic smem (3 stages).
template<int BM, int BN, int WARPS_M, int WARPS_N, int EPI>
__global__ void __launch_bounds__(WARPS_M * WARPS_N * 32)
k_mmab(const __nv_bfloat16* __restrict__ A, int lda, long strideAz,
       const __nv_bfloat16* __restrict__ Bg, int ldb, long strideBz,
       float* __restrict__ C, int ldc, long strideCz, int K) {
    constexpr int BK = 32;
    constexpr int LDP = 20;               // 80B row stride: 16B aligned, conflict-free
    constexpr int NS  = 3;
    constexpr int T  = WARPS_M * WARPS_N * 32;
    constexpr int WTM = BM / WARPS_M;
    constexpr int WTN = BN / WARPS_N;
    constexpr int MT  = WTM / 16;
    constexpr int NT  = WTN / 8;
    static_assert(NT % 2 == 0, "NT must be even for paired B ldmatrix");

    extern __shared__ uint32_t dyn[];
    typedef uint32_t ATile[BM][LDP];
    typedef uint32_t BTile[BN][LDP];
    ATile* As2 = (ATile*)dyn;
    BTile* Bs2 = (BTile*)(dyn + NS * BM * LDP);

    int tid = threadIdx.x, lane = tid & 31, wid = tid >> 5;
    int wm = wid % WARPS_M, wn = wid / WARPS_M;
    int m0 = blockIdx.y * BM, n0 = blockIdx.x * BN;
    int z = blockIdx.z;
    int tig = lane & 3, grp = lane >> 2;

    const __nv_bfloat16* Ap = A + (long)z * strideAz;
    const __nv_bfloat16* Bp = Bg + (long)z * strideBz;
    float* Cp = C + (long)z * strideCz;

    int a_row_off = (lane & 7) + ((lane >> 3) & 1) * 8;
    int a_col_off = ((lane >> 4) & 1) * 4;
    int b_row_off = (lane & 7) + ((lane >> 4) & 1) * 8;
    int b_col_off = ((lane >> 3) & 1) * 4;

    float acc[MT][NT][4];
    #pragma unroll
    for (int i = 0; i < MT; i++)
        #pragma unroll
        for (int j = 0; j < NT; j++)
            #pragma unroll
            for (int q = 0; q < 4; q++) acc[i][j][q] = 0.f;

    auto load_tiles = [&](int st, int k0) {
        #pragma unroll 2
        for (int idx = tid; idx < BM * 4; idx += T) {
            int m = idx >> 2, c = idx & 3;
            cp16(&As2[st][m][c * 4], Ap + (size_t)(m0 + m) * lda + k0 + c * 8);
        }
        #pragma unroll 2
        for (int idx = tid; idx < BN * 4; idx += T) {
            int n = idx >> 2, c = idx & 3;
            cp16(&Bs2[st][n][c * 4], Bp + (size_t)(n0 + n) * ldb + k0 + c * 8);
        }
    };

    int KT = K / BK;
    load_tiles(0, 0);
    CP_COMMIT();
    load_tiles(1, BK);
    CP_COMMIT();
    int st = 0;
    for (int kt = 0; kt < KT; kt++) {
        if (kt + 2 < KT) {
            int s2 = st + 2; if (s2 >= NS) s2 -= NS;
            load_tiles(s2, (kt + 2) * BK);
        }
        CP_COMMIT();
        CP_WAIT2();
        __syncthreads();

        uint32_t aBase = (uint32_t)__cvta_generic_to_shared(&As2[st][0][0]);
        uint32_t bBase = (uint32_t)__cvta_generic_to_shared(&Bs2[st][0][0]);
        #pragma unroll
        for (int ks = 0; ks < 2; ks++) {
            int pb = ks * 8;
            uint32_t afr[MT][4], bfr[NT][2];
            #pragma unroll
            for (int i = 0; i < MT; i++) {
                int r = wm * WTM + i * 16;
                uint32_t addr = aBase +
                    (uint32_t)(((r + a_row_off) * LDP + pb + a_col_off) * 4);
                ldsm4(afr[i][0], afr[i][1], afr[i][2], afr[i][3], addr);
            }
            #pragma unroll
            for (int j = 0; j < NT; j += 2) {
                int nb = wn * WTN + j * 8;
                uint32_t addr = bBase +
                    (uint32_t)(((nb + b_row_off) * LDP + pb + b_col_off) * 4);
                ldsm4(bfr[j][0], bfr[j][1], bfr[j + 1][0], bfr[j + 1][1], addr);
            }
            #pragma unroll
            for (int i = 0; i < MT; i++)
                #pragma unroll
                for (int j = 0; j < NT; j++)
                    mma16(acc[i][j], afr[i], bfr[j]);
        }
        __syncthreads();
        if (++st >= NS) st = 0;
    }

    #pragma unroll
    for (int i = 0; i < MT; i++) {
        #pragma unroll
        for (int half = 0; half < 2; half++) {
            int r = m0 + wm * WTM + i * 16 + grp + half * 8;
            #pragma unroll
            for (int j = 0; j < NT; j++) {
                int n = n0 + wn * WTN + j * 8 + tig * 2;
                float v0 = acc[i][j][half * 2 + 0];
                float v1 = acc[i][j][half * 2 + 1];
                float* cp = Cp + (size_t)r * ldc + n;
                if (EPI == 2) {
                    cp[0] += v0;
                    cp[1] += v1;
                } else {
                    *(float2*)cp = make_float2(v0, v1);
                }
            }
        }
    }
}
#define MMAB_SMEM (3 * (128 * 20 + 128 * 20) * 4)

// ---------------- tf32 MMA GEMM (x_proj) -------------------------------------
template<int BM, int BN, int WARPS_M, int WARPS_N>
__global__ void __launch_bounds__(WARPS_M * WARPS_N * 32)
k_mma(const float* __restrict__ A, int lda, long strideAz,
      const float* __restrict__ Bg, int ldb, long strideBz,
      float* __restrict__ C, int ldc, long strideCz, int K) {
    constexpr int BK = 16;
    constexpr int T  = WARPS_M * WARPS_N * 32;
    constexpr int WTM = BM / WARPS_M;
    constexpr int WTN = BN / WARPS_N;
    constexpr int MT  = WTM / 16;
    constexpr int NT  = WTN / 8;

    __shared__ float As[2][BM][BK + 4];
    __shared__ float Bs[2][BK][BN + 8];

    int tid = threadIdx.x, lane = tid & 31, wid = tid >> 5;
    int wm = wid % WARPS_M, wn = wid / WARPS_M;
    int m0 = blockIdx.y * BM, n0 = blockIdx.x * BN;
    int z = blockIdx.z;
    int tig = lane & 3, grp = lane >> 2;

    const float* Ap = A + (long)z * strideAz;
    const float* Bp = Bg + (long)z * strideBz;
    float* Cp = C + (long)z * strideCz;

    float acc[MT][NT][4];
    #pragma unroll
    for (int i = 0; i < MT; i++)
        #pragma unroll
        for (int j = 0; j < NT; j++)
            #pragma unroll
            for (int q = 0; q < 4; q++) acc[i][j][q] = 0.f;

    auto load_tiles = [&](int st, int k0) {
        #pragma unroll 2
        for (int idx = tid; idx < BM * 4; idx += T) {
            int m = idx >> 2, kq = idx & 3;
            cp16(&As[st][m][kq * 4], Ap + (size_t)(m0 + m) * lda + k0 + kq * 4);
        }
        #pragma unroll 2
        for (int idx = tid; idx < BK * BN / 4; idx += T) {
            int k = idx / (BN / 4), nq = idx % (BN / 4);
            cp16(&Bs[st][k][nq * 4], Bp + (size_t)(k0 + k) * ldb + n0 + nq * 4);
        }
    };

    int KT = K / BK;
    load_tiles(0, 0);
    CP_COMMIT();
    for (int kt = 0; kt < KT; kt++) {
        if (kt + 1 < KT) load_tiles((kt + 1) & 1, (kt + 1) * BK);
        CP_COMMIT();
        CP_WAIT1();
        __syncthreads();
        int st = kt & 1;
        #pragma unroll
        for (int ks = 0; ks < 2; ks++) {
            int c = ks * 8 + tig;
            uint32_t afr[MT][4], bfr[NT][2];
            #pragma unroll
            for (int i = 0; i < MT; i++) {
                int r = wm * WTM + i * 16 + grp;
                afr[i][0] = f2tf(As[st][r][c]);
                afr[i][1] = f2tf(As[st][r + 8][c]);
                afr[i][2] = f2tf(As[st][r][c + 4]);
                afr[i][3] = f2tf(As[st][r + 8][c + 4]);
            }
            #pragma unroll
            for (int j = 0; j < NT; j++) {
                int nb = wn * WTN + j * 8 + grp;
                bfr[j][0] = f2tf(Bs[st][c][nb]);
                bfr[j][1] = f2tf(Bs[st][c + 4][nb]);
            }
            #pragma unroll
            for (int i = 0; i < MT; i++)
                #pragma unroll
                for (int j = 0; j < NT; j++)
                    mma8(acc[i][j], afr[i], bfr[j]);
        }
        __syncthreads();
    }

    #pragma unroll
    for (int i = 0; i < MT; i++) {
        #pragma unroll
        for (int half = 0; half < 2; half++) {
            int r = m0 + wm * WTM + i * 16 + grp + half * 8;
            #pragma unroll
            for (int j = 0; j < NT; j++) {
                int n = n0 + wn * WTN + j * 8 + tig * 2;
                *(float2*)(Cp + (size_t)r * ldc + n) =
                    make_float2(acc[i][j][half * 2 + 0], acc[i][j][half * 2 + 1]);
            }
        }
    }
}

// -------- patch embed + LN + pos: PGROW rows per CTA (weight reuse) ----------
__global__ void __launch_bounds__(512)
k_patch(const float* __restrict__ x,
        const float* __restrict__ bng, const float* __restrict__ bnb,
        const float* __restrict__ bnm, const float* __restrict__ bnv,
        const float* __restrict__ pb,
        const float* __restrict__ lg,  const float* __restrict__ lb,
        const float* __restrict__ pos) {
    __shared__ float p[PGROW][KPATCH + 2];
    __shared__ float sm[17];
    int row0 = blockIdx.x * PGROW, tid = threadIdx.x;

    for (int e = tid; e < PGROW * KPATCH; e += 512) {
        int g = e / KPATCH, k = e - g * KPATCH;
        int row = row0 + g;
        int b = row >> 4, l = row & 15;
        int c = k / PATCH, j = k - c * PATCH;
        float xv = x[(b * C_IN + c) * T_LEN + l * PATCH + j];
        p[g][k] = (xv - bnm[c]) * rsqrtf(bnv[c] + EPS) * bng[c] + bnb[c];
    }
    __syncthreads();

    float acc[PGROW];
    float bias = pb[tid];
    #pragma unroll
    for (int g = 0; g < PGROW; g++) acc[g] = bias;
    const float* wt = g_pwt + tid;
    #pragma unroll 2
    for (int k = 0; k < KPATCH; k++) {
        float w = wt[(size_t)k * D_MODEL];
        #pragma unroll
        for (int g = 0; g < PGROW; g++) acc[g] = fmaf(p[g][k], w, acc[g]);
    }
    float gv = lg[tid], bv = lb[tid];
    #pragma unroll 1
    for (int g = 0; g < PGROW; g++) {
        int row = row0 + g;
        int l = row & 15;
        float mean = block_sum_512(acc[g], sm) * (1.f / D_MODEL);
        float df = acc[g] - mean;
        float var = block_sum_512(df * df, sm) * (1.f / D_MODEL);
        g_h[(size_t)row * D_MODEL + tid] =
            df * rsqrtf(var + EPS) * gv + bv + pos[l * D_MODEL + tid];
    }
}

// ---------------- LayerNorm: fp32 in -> bf16 out -----------------------------
__global__ void k_ln_bf(const float* __restrict__ in, __nv_bfloat16* __restrict__ out,
                        const float* __restrict__ g, const float* __restrict__ b) {
    __shared__ float sm[17];
    int row = blockIdx.x, tid = threadIdx.x;
    float v = in[row * D_MODEL + tid];
    float mean = block_sum_512(v, sm) * (1.f / D_MODEL);
    float df = v - mean;
    float var = block_sum_512(df * df, sm) * (1.f / D_MODEL);
    out[row * D_MODEL + tid] =
        __float2bfloat16(df * rsqrtf(var + EPS) * g[tid] + b[tid]);
}

// ---------------- LayerNorm: fp32 -> fp32 (final) ----------------------------
__global__ void k_ln(const float* __restrict__ in, float* __restrict__ out,
                     const float* __restrict__ g, const float* __restrict__ b) {
    __shared__ float sm[17];
    int row = blockIdx.x, tid = threadIdx.x;
    float v = in[row * D_MODEL + tid];
    float mean = block_sum_512(v, sm) * (1.f / D_MODEL);
    float df = v - mean;
    float var = block_sum_512(df * df, sm) * (1.f / D_MODEL);
    out[row * D_MODEL + tid] = df * rsqrtf(var + EPS) * g[tid] + b[tid];
}

// ---------------- causal depthwise conv + SiLU, both dirs -------------------
__global__ void k_conv(const float* __restrict__ cw, const float* __restrict__ cb) {
    int dir = blockIdx.z;
    int idx = blockIdx.x * 256 + threadIdx.x;
    int b = idx >> 10;
    int d = idx & (D_INNER - 1);
    const float* u = g_uz + (size_t)dir * M_ROWS * 2 * D_INNER
                   + (size_t)(b * L_TK) * (2 * D_INNER) + d;
    float* o = g_uc + (size_t)dir * M_ROWS * D_INNER
             + (size_t)(b * L_TK) * D_INNER + d;
    const float* cwd = cw + (size_t)dir * D_INNER * D_CONV;
    const float* cbd = cb + (size_t)dir * D_INNER;
    float w0 = cwd[d * D_CONV + 0], w1 = cwd[d * D_CONV + 1];
    float w2 = cwd[d * D_CONV + 2], w3 = cwd[d * D_CONV + 3];
    float bias = cbd[d];
    float h0 = 0.f, h1 = 0.f, h2 = 0.f;
    #pragma unroll
    for (int l = 0; l < L_TK; l++) {
        int j = dir ? (15 - l) : l;
        float cur = u[(size_t)j * (2 * D_INNER)];
        float a = bias;
        a = fmaf(w0, h0, a);
        a = fmaf(w1, h1, a);
        a = fmaf(w2, h2, a);
        a = fmaf(w3, cur, a);
        o[(size_t)l * D_INNER] = a / (1.f + __expf(-a));
        h0 = h1; h1 = h2; h2 = cur;
    }
}

// ---------------- fused dt_proj + softplus + scan + D skip + gate ------------
__global__ void k_scan(const float* __restrict__ Wdt, const float* __restrict__ bdt,
                       const float* __restrict__ Alog, const float* __restrict__ Dv) {
    __shared__ ull B2[L_TK][8], C2[L_TK][8];
    __shared__ float dtr[L_TK][DT_RANK];
    int dir = blockIdx.z;
    int b = blockIdx.x;
    int tid = threadIdx.x;
    int d = blockIdx.y * 256 + tid;

    const float* proj = g_proj + (size_t)dir * M_ROWS * PROJW;
    const float* ucp  = g_uc   + (size_t)dir * M_ROWS * D_INNER;
    const float* uzp  = g_uz   + (size_t)dir * M_ROWS * 2 * D_INNER;
    const float* Wdtd = Wdt  + (size_t)dir * DT_RANK * D_INNER;
    const float* bdtd = bdt  + (size_t)dir * D_INNER;
    const float* Al   = Alog + (size_t)dir * D_INNER * D_STATE;
    const float* Dp   = Dv   + (size_t)dir * D_INNER;

    for (int e = tid; e < L_TK * 8; e += 256) {
        int l = e >> 3, p = e & 7;
        const float* pr = proj + (size_t)(b * L_TK + l) * PROJW;
        float2 vb = *(const float2*)(pr + DT_RANK + p * 2);
        float2 vc = *(const float2*)(pr + DT_RANK + D_STATE + p * 2);
        B2[l][p] = pk2(vb.x, vb.y);
        C2[l][p] = pk2(vc.x, vc.y);
    }
    for (int e = tid; e < L_TK * DT_RANK; e += 256) {
        int l = e >> 5, k = e & 31;
        dtr[l][k] = proj[(size_t)(b * L_TK + l) * PROJW + k];
    }
    __syncthreads();

    float dtv[L_TK];
    {
        float bias = bdtd[d];
        #pragma unroll
        for (int l = 0; l < L_TK; l++) dtv[l] = bias;
        #pragma unroll 4
        for (int k = 0; k < DT_RANK; k++) {
            float w = Wdtd[(size_t)k * D_INNER + d];
            #pragma unroll
            for (int l = 0; l < L_TK; l++) dtv[l] = fmaf(dtr[l][k], w, dtv[l]);
        }
        #pragma unroll
        for (int l = 0; l < L_TK; l++) dtv[l] = softplusf(dtv[l]);
    }

    float A[D_STATE];
    bool ok = true;
    #pragma unroll
    for (int n = 0; n < D_STATE; n++) {
        A[n] = -__expf(Al[(size_t)d * D_STATE + n]);
        ok = ok && (fabsf(A[n] + (float)(n + 1)) < 2e-3f);
    }
    float Dd = Dp[d];

    if (ok) {
        ull st[8];
        #pragma unroll
        for (int p = 0; p < 8; p++) st[p] = pk2(0.f, 0.f);
        for (int l = 0; l < L_TK; l++) {
            int rp = b * L_TK + l;
            int rn = b * L_TK + (dir ? (15 - l) : l);
            float dt = dtv[l];
            float u  = ucp[(size_t)rp * D_INNER + d];
            float du = dt * u;
            float q  = __expf(-dt);
            float qq = q * q;
            ull w    = pk2(q, qq);
            ull step = pk2(qq, qq);
            ull du2  = pk2(du, du);
            ull y2   = pk2(0.f, 0.f);
            #pragma unroll
            for (int p = 0; p < 8; p++) {
                st[p] = fma2(st[p], w, mul2(du2, B2[l][p]));
                y2 = fma2(st[p], C2[l][p], y2);
                w = mul2(w, step);
            }
            float ylo, yhi;
            upk2(y2, ylo, yhi);
            float y = ylo + yhi + u * Dd;
            float zv = uzp[(size_t)rn * (2 * D_INNER) + D_INNER + d];
            g_ysb[(size_t)rn * (2 * D_INNER) + dir * D_INNER + d] =
                __float2bfloat16(y * (zv / (1.f + __expf(-zv))));
        }
    } else {
        float st[D_STATE];
        #pragma unroll
        for (int n = 0; n < D_STATE; n++) st[n] = 0.f;
        for (int l = 0; l < L_TK; l++) {
            int rp = b * L_TK + l;
            int rn = b * L_TK + (dir ? (15 - l) : l);
            float dt = dtv[l];
            float u  = ucp[(size_t)rp * D_INNER + d];
            float du = dt * u;
            float y = 0.f;
            #pragma unroll
            for (int n = 0; n < D_STATE; n++) {
                float blo, bhi, clo, chi;
                upk2(B2[l][n >> 1], blo, bhi);
                upk2(C2[l][n >> 1], clo, chi);
                float Bv = (n & 1) ? bhi : blo;
                float Cv = (n & 1) ? chi : clo;
                float s = fmaf(st[n], __expf(dt * A[n]), du * Bv);
                st[n] = s;
                y = fmaf(s, Cv, y);
            }
            y = fmaf(u, Dd, y);
            float zv = uzp[(size_t)rn * (2 * D_INNER) + D_INNER + d];
            g_ysb[(size_t)rn * (2 * D_INNER) + dir * D_INNER + d] =
                __float2bfloat16(y * (zv / (1.f + __expf(-zv))));
        }
    }
}

// ---------------- launch -----------------------------------------------------
extern "C" void kernel_launch(void* const* d_in, const int* in_sizes, int n_in,
                              void* d_out, int out_size) {
    const float* x    = (const float*)d_in[0];
    const float* bng  = (const float*)d_in[1];
    const float* bnb  = (const float*)d_in[2];
    const float* bnm  = (const float*)d_in[3];
    const float* bnv  = (const float*)d_in[4];
    const float* pw   = (const float*)d_in[5];
    const float* pb   = (const float*)d_in[6];
    const float* lpg  = (const float*)d_in[7];
    const float* lpb  = (const float*)d_in[8];
    const float* pos  = (const float*)d_in[9];
    const float* blg  = (const float*)d_in[10];
    const float* blb  = (const float*)d_in[11];
    const float* Wi   = (const float*)d_in[12];
    const float* cw   = (const float*)d_in[13];
    const float* cb   = (const float*)d_in[14];
    const float* Wx   = (const float*)d_in[15];
    const float* Wdt  = (const float*)d_in[16];
    const float* bdt  = (const float*)d_in[17];
    const float* Alog = (const float*)d_in[18];
    const float* Dv   = (const float*)d_in[19];
    const float* Wo   = (const float*)d_in[20];
    const float* flg  = (const float*)d_in[21];
    const float* flb  = (const float*)d_in[22];
    float* out = (float*)d_out;

    float *ph, *puz, *puc, *pproj, *ppwt;
    __nv_bfloat16 *phnb, *pysb, *pwib, *pwob;
    cudaGetSymbolAddress((void**)&ph,   g_h);
    cudaGetSymbolAddress((void**)&puz,  g_uz);
    cudaGetSymbolAddress((void**)&puc,  g_uc);
    cudaGetSymbolAddress((void**)&pproj,g_proj);
    cudaGetSymbolAddress((void**)&ppwt, g_pwt);
    cudaGetSymbolAddress((void**)&phnb, g_hnb);
    cudaGetSymbolAddress((void**)&pysb, g_ysb);
    cudaGetSymbolAddress((void**)&pwib, g_wib);
    cudaGetSymbolAddress((void**)&pwob, g_wob);

    static int attr_done = 0;
    if (!attr_done) {
        cudaFuncSetAttribute(k_mmab<128,128,2,4,0>,
                             cudaFuncAttributeMaxDynamicSharedMemorySize, MMAB_SMEM);
        cudaFuncSetAttribute(k_mmab<128,128,2,4,2>,
                             cudaFuncAttributeMaxDynamicSharedMemorySize, MMAB_SMEM);
        attr_done = 1;
    }

    // weight transpose-convert
    k_tb<<<dim3(2 * D_INNER / 32, D_MODEL / 32, 4), dim3(32, 8)>>>(
        Wi, pwib, D_MODEL, 2 * D_INNER);
    k_tb<<<dim3(D_MODEL / 32, 2 * D_INNER / 32, 2), dim3(32, 8)>>>(
        Wo, pwob, 2 * D_INNER, D_MODEL);
    k_tpw<<<KPATCH, D_MODEL>>>(pw, ppwt);

    k_patch<<<M_ROWS / PGROW, 512>>>(x, bng, bnb, bnm, bnv, pb, lpg, lpb, pos);

    for (int i = 0; i < 2; i++) {
        k_ln_bf<<<M_ROWS, 512>>>(ph, phnb, blg + i * D_MODEL, blb + i * D_MODEL);

        // in_proj both dirs: bf16 (4096,512)@(512,2048) -> g_uz[dir]
        k_mmab<128,128,2,4,0>
            <<<dim3(2 * D_INNER / 128, M_ROWS / 128, 2), 256, MMAB_SMEM>>>(
            phnb, D_MODEL, 0,
            pwib + (size_t)i * 2 * 2 * D_INNER * D_MODEL, D_MODEL,
            (long)2 * D_INNER * D_MODEL,
            puz, 2 * D_INNER, (long)M_ROWS * 2 * D_INNER,
            D_MODEL);

        // conv + SiLU both dirs
        k_conv<<<dim3((B_SZ * D_INNER) / 256, 1, 2), 256>>>(
            cw + (size_t)i * 2 * D_INNER * D_CONV, cb + (size_t)i * 2 * D_INNER);

        // x_proj both dirs: tf32 (4096,1024)@(1024,64) -> g_proj[dir]
        k_mma<64,64,2,2><<<dim3(1, M_ROWS / 64, 2), 128>>>(
            puc, D_INNER, (long)M_ROWS * D_INNER,
            Wx + (size_t)i * 2 * D_INNER * PROJW, PROJW, (long)D_INNER * PROJW,
            pproj, PROJW, (long)M_ROWS * PROJW,
            D_INNER);

        // fused dt_proj + scan both dirs -> g_ysb (bf16)
        k_scan<<<dim3(B_SZ, D_INNER / 256, 2), 256>>>(
            Wdt  + (size_t)i * 2 * DT_RANK * D_INNER,
            bdt  + (size_t)i * 2 * D_INNER,
            Alog + (size_t)i * 2 * D_INNER * D_STATE,
            Dv   + (size_t)i * 2 * D_INNER);

        // out_proj: bf16 (4096,2048)@(2048,512) += g_h
        k_mmab<128,128,2,4,2>
            <<<dim3(D_MODEL / 128, M_ROWS / 128, 1), 256, MMAB_SMEM>>>(
            pysb, 2 * D_INNER, 0,
            pwob + (size_t)i * 2 * D_INNER * D_MODEL, 2 * D_INNER, 0,
            ph, D_MODEL, 0,
            2 * D_INNER);
    }
    k_ln<<<M_ROWS, 512>>>(ph, out, flg, flb);
}

// round 15
// speedup vs baseline: 1.6959x; 1.0002x over previous
#include <cuda_runtime.h>
#include <cuda_bf16.h>
#include <math.h>
#include <stdint.h>

#define B_SZ   256
#define C_IN   7
#define T_LEN  160
#define PATCH  10
#define L_TK   16
#define D_MODEL 512
#define D_INNER 1024
#define D_STATE 16
#define DT_RANK 32
#define D_CONV  4
#define M_ROWS (B_SZ * L_TK)          // 4096
#define PROJW  (DT_RANK + 2*D_STATE)  // 64
#define KPATCH (C_IN * PATCH)         // 70
#define PGROW  8                      // rows per patch CTA
#define EPS 1e-5f

// ---------------- scratch ----------------------------------------------------
__device__ float g_h  [M_ROWS * D_MODEL];
__device__ float g_uz [2 * M_ROWS * 2 * D_INNER];
__device__ float g_uc [2 * M_ROWS * D_INNER];
__device__ float g_proj[2 * M_ROWS * PROJW];
__device__ float g_pwt[KPATCH * D_MODEL];                    // transposed patch_w
__device__ __nv_bfloat16 g_hnb[M_ROWS * D_MODEL];
__device__ __nv_bfloat16 g_ysb[M_ROWS * 2 * D_INNER];        // [row][dir*1024+d]
__device__ __nv_bfloat16 g_wib[4 * 2 * D_INNER * D_MODEL];   // 4 x [2048][512]
__device__ __nv_bfloat16 g_wob[2 * 2 * D_INNER * D_MODEL];   // 2 x [512][2048]

// ---------------- helpers ----------------------------------------------------
__device__ __forceinline__ uint32_t f2tf(float x) {
    uint32_t r; asm("cvt.rna.tf32.f32 %0, %1;" : "=r"(r) : "f"(x)); return r;
}
__device__ __forceinline__ void mma8(float* c, const uint32_t* a, const uint32_t* b) {
    asm volatile(
        "mma.sync.aligned.m16n8k8.row.col.f32.tf32.tf32.f32 "
        "{%0,%1,%2,%3},{%4,%5,%6,%7},{%8,%9},{%0,%1,%2,%3};"
        : "+f"(c[0]), "+f"(c[1]), "+f"(c[2]), "+f"(c[3])
        : "r"(a[0]), "r"(a[1]), "r"(a[2]), "r"(a[3]), "r"(b[0]), "r"(b[1]));
}
__device__ __forceinline__ void mma16(float* c, const uint32_t* a, const uint32_t* b) {
    asm volatile(
        "mma.sync.aligned.m16n8k16.row.col.f32.bf16.bf16.f32 "
        "{%0,%1,%2,%3},{%4,%5,%6,%7},{%8,%9},{%0,%1,%2,%3};"
        : "+f"(c[0]), "+f"(c[1]), "+f"(c[2]), "+f"(c[3])
        : "r"(a[0]), "r"(a[1]), "r"(a[2]), "r"(a[3]), "r"(b[0]), "r"(b[1]));
}
__device__ __forceinline__ void ldsm4(uint32_t& r0, uint32_t& r1, uint32_t& r2,
                                      uint32_t& r3, uint32_t addr) {
    asm volatile("ldmatrix.sync.aligned.m8n8.x4.shared.b16 {%0,%1,%2,%3}, [%4];"
                 : "=r"(r0), "=r"(r1), "=r"(r2), "=r"(r3) : "r"(addr));
}
__device__ __forceinline__ float softplusf(float v) {
    return fmaxf(v, 0.f) + log1pf(__expf(-fabsf(v)));
}
__device__ __forceinline__ void cp16(void* dst, const void* src) {
    uint32_t d = (uint32_t)__cvta_generic_to_shared(dst);
    asm volatile("cp.async.cg.shared.global [%0], [%1], 16;" :: "r"(d), "l"(src));
}
#define CP_COMMIT() asm volatile("cp.async.commit_group;")
#define CP_WAIT1()  asm volatile("cp.async.wait_group 1;")
#define CP_WAIT2()  asm volatile("cp.async.wait_group 2;")

typedef unsigned long long ull;
__device__ __forceinline__ ull pk2(float x, float y) {
    ull r; asm("mov.b64 %0, {%1,%2};" : "=l"(r) : "f"(x), "f"(y)); return r;
}
__device__ __forceinline__ void upk2(ull v, float& x, float& y) {
    asm("mov.b64 {%0,%1}, %2;" : "=f"(x), "=f"(y) : "l"(v));
}
__device__ __forceinline__ ull fma2(ull a, ull b, ull c) {
    ull d; asm("fma.rn.f32x2 %0, %1, %2, %3;" : "=l"(d) : "l"(a), "l"(b), "l"(c)); return d;
}
__device__ __forceinline__ ull mul2(ull a, ull b) {
    ull d; asm("mul.rn.f32x2 %0, %1, %2;" : "=l"(d) : "l"(a), "l"(b)); return d;
}

__device__ __forceinline__ float block_sum_512(float v, float* sm) {
    int tid = threadIdx.x;
    #pragma unroll
    for (int o = 16; o; o >>= 1) v += __shfl_xor_sync(0xffffffffu, v, o);
    if ((tid & 31) == 0) sm[tid >> 5] = v;
    __syncthreads();
    if (tid == 0) {
        float s = 0.f;
        #pragma unroll
        for (int i = 0; i < 16; i++) s += sm[i];
        sm[16] = s;
    }
    __syncthreads();
    float r = sm[16];
    __syncthreads();
    return r;
}

// ---------------- transpose + convert weights to bf16 ------------------------
__global__ void k_tb(const float* __restrict__ src, __nv_bfloat16* __restrict__ dst,
                     int K, int N) {
    __shared__ __nv_bfloat16 t[32][33];
    long zo = (long)blockIdx.z * K * N;
    int n0 = blockIdx.x * 32, k0 = blockIdx.y * 32;
    for (int i = threadIdx.y; i < 32; i += 8)
        t[i][threadIdx.x] = __float2bfloat16(src[zo + (size_t)(k0 + i) * N + n0 + threadIdx.x]);
    __syncthreads();
    for (int i = threadIdx.y; i < 32; i += 8)
        dst[zo + (size_t)(n0 + i) * K + k0 + threadIdx.x] = t[threadIdx.x][i];
}

// ---------------- transpose patch_w [512][70] -> [70][512] -------------------
__global__ void k_tpw(const float* __restrict__ src, float* __restrict__ dst) {
    int k = blockIdx.x;                // 0..69
    int n = threadIdx.x;               // 0..511
    dst[k * D_MODEL + n] = src[(size_t)n * KPATCH + k];
}

// ---------------- 3-stage bf16 MMA GEMM with ldmatrix ------------------------
// A [M][K] bf16 row-major, B [N][K] bf16 row-major (pre-transposed weights).
// EPI: 0 = store fp32, 2 = accumulate fp32. Dynamic smem (3 stages).
template<int BM, int BN, int WARPS_M, int WARPS_N, int EPI>
__global__ void __launch_bounds__(WARPS_M * WARPS_N * 32)
k_mmab(const __nv_bfloat16* __restrict__ A, int lda, long strideAz,
       const __nv_bfloat16* __restrict__ Bg, int ldb, long strideBz,
       float* __restrict__ C, int ldc, long strideCz, int K) {
    constexpr int BK = 32;
    constexpr int LDP = 20;               // 80B row stride: 16B aligned, conflict-free
    constexpr int NS  = 3;
    constexpr int T  = WARPS_M * WARPS_N * 32;
    constexpr int WTM = BM / WARPS_M;
    constexpr int WTN = BN / WARPS_N;
    constexpr int MT  = WTM / 16;
    constexpr int NT  = WTN / 8;
    static_assert(NT % 2 == 0, "NT must be even for paired B ldmatrix");

    extern __shared__ uint32_t dyn[];
    typedef uint32_t ATile[BM][LDP];
    typedef uint32_t BTile[BN][LDP];
    ATile* As2 = (ATile*)dyn;
    BTile* Bs2 = (BTile*)(dyn + NS * BM * LDP);

    int tid = threadIdx.x, lane = tid & 31, wid = tid >> 5;
    int wm = wid % WARPS_M, wn = wid / WARPS_M;
    int m0 = blockIdx.y * BM, n0 = blockIdx.x * BN;
    int z = blockIdx.z;
    int tig = lane & 3, grp = lane >> 2;

    const __nv_bfloat16* Ap = A + (long)z * strideAz;
    const __nv_bfloat16* Bp = Bg + (long)z * strideBz;
    float* Cp = C + (long)z * strideCz;

    int a_row_off = (lane & 7) + ((lane >> 3) & 1) * 8;
    int a_col_off = ((lane >> 4) & 1) * 4;
    int b_row_off = (lane & 7) + ((lane >> 4) & 1) * 8;
    int b_col_off = ((lane >> 3) & 1) * 4;

    float acc[MT][NT][4];
    #pragma unroll
    for (int i = 0; i < MT; i++)
        #pragma unroll
        for (int j = 0; j < NT; j++)
            #pragma unroll
            for (int q = 0; q < 4; q++) acc[i][j][q] = 0.f;

    auto load_tiles = [&](int st, int k0) {
        #pragma unroll 2
        for (int idx = tid; idx < BM * 4; idx += T) {
            int m = idx >> 2, c = idx & 3;
            cp16(&As2[st][m][c * 4], Ap + (size_t)(m0 + m) * lda + k0 + c * 8);
        }
        #pragma unroll 2
        for (int idx = tid; idx < BN * 4; idx += T) {
            int n = idx >> 2, c = idx & 3;
            cp16(&Bs2[st][n][c * 4], Bp + (size_t)(n0 + n) * ldb + k0 + c * 8);
        }
    };

    int KT = K / BK;
    load_tiles(0, 0);
    CP_COMMIT();
    load_tiles(1, BK);
    CP_COMMIT();
    int st = 0;
    for (int kt = 0; kt < KT; kt++) {
        if (kt + 2 < KT) {
            int s2 = st + 2; if (s2 >= NS) s2 -= NS;
            load_tiles(s2, (kt + 2) * BK);
        }
        CP_COMMIT();
        CP_WAIT2();
        __syncthreads();

        uint32_t aBase = (uint32_t)__cvta_generic_to_shared(&As2[st][0][0]);
        uint32_t bBase = (uint32_t)__cvta_generic_to_shared(&Bs2[st][0][0]);
        #pragma unroll
        for (int ks = 0; ks < 2; ks++) {
            int pb = ks * 8;
            uint32_t afr[MT][4], bfr[NT][2];
            #pragma unroll
            for (int i = 0; i < MT; i++) {
                int r = wm * WTM + i * 16;
                uint32_t addr = aBase +
                    (uint32_t)(((r + a_row_off) * LDP + pb + a_col_off) * 4);
                ldsm4(afr[i][0], afr[i][1], afr[i][2], afr[i][3], addr);
            }
            #pragma unroll
            for (int j = 0; j < NT; j += 2) {
                int nb = wn * WTN + j * 8;
                uint32_t addr = bBase +
                    (uint32_t)(((nb + b_row_off) * LDP + pb + b_col_off) * 4);
                ldsm4(bfr[j][0], bfr[j][1], bfr[j + 1][0], bfr[j + 1][1], addr);
            }
            #pragma unroll
            for (int i = 0; i < MT; i++)
                #pragma unroll
                for (int j = 0; j < NT; j++)
                    mma16(acc[i][j], afr[i], bfr[j]);
        }
        __syncthreads();
        if (++st >= NS) st = 0;
    }

    #pragma unroll
    for (int i = 0; i < MT; i++) {
        #pragma unroll
        for (int half = 0; half < 2; half++) {
            int r = m0 + wm * WTM + i * 16 + grp + half * 8;
            #pragma unroll
            for (int j = 0; j < NT; j++) {
                int n = n0 + wn * WTN + j * 8 + tig * 2;
                float v0 = acc[i][j][half * 2 + 0];
                float v1 = acc[i][j][half * 2 + 1];
                float* cp = Cp + (size_t)r * ldc + n;
                if (EPI == 2) {
                    cp[0] += v0;
                    cp[1] += v1;
                } else {
                    *(float2*)cp = make_float2(v0, v1);
                }
            }
        }
    }
}
#define MMAB_SMEM  (3 * (128 * 20 + 128 * 20) * 4)
#define MMAB_SMEM64 (3 * (64 * 20 + 128 * 20) * 4)

// ---------------- tf32 MMA GEMM (x_proj) -------------------------------------
template<int BM, int BN, int WARPS_M, int WARPS_N>
__global__ void __launch_bounds__(WARPS_M * WARPS_N * 32)
k_mma(const float* __restrict__ A, int lda, long strideAz,
      const float* __restrict__ Bg, int ldb, long strideBz,
      float* __restrict__ C, int ldc, long strideCz, int K) {
    constexpr int BK = 16;
    constexpr int T  = WARPS_M * WARPS_N * 32;
    constexpr int WTM = BM / WARPS_M;
    constexpr int WTN = BN / WARPS_N;
    constexpr int MT  = WTM / 16;
    constexpr int NT  = WTN / 8;

    __shared__ float As[2][BM][BK + 4];
    __shared__ float Bs[2][BK][BN + 8];

    int tid = threadIdx.x, lane = tid & 31, wid = tid >> 5;
    int wm = wid % WARPS_M, wn = wid / WARPS_M;
    int m0 = blockIdx.y * BM, n0 = blockIdx.x * BN;
    int z = blockIdx.z;
    int tig = lane & 3, grp = lane >> 2;

    const float* Ap = A + (long)z * strideAz;
    const float* Bp = Bg + (long)z * strideBz;
    float* Cp = C + (long)z * strideCz;

    float acc[MT][NT][4];
    #pragma unroll
    for (int i = 0; i < MT; i++)
        #pragma unroll
        for (int j = 0; j < NT; j++)
            #pragma unroll
            for (int q = 0; q < 4; q++) acc[i][j][q] = 0.f;

    auto load_tiles = [&](int st, int k0) {
        #pragma unroll 2
        for (int idx = tid; idx < BM * 4; idx += T) {
            int m = idx >> 2, kq = idx & 3;
            cp16(&As[st][m][kq * 4], Ap + (size_t)(m0 + m) * lda + k0 + kq * 4);
        }
        #pragma unroll 2
        for (int idx = tid; idx < BK * BN / 4; idx += T) {
            int k = idx / (BN / 4), nq = idx % (BN / 4);
            cp16(&Bs[st][k][nq * 4], Bp + (size_t)(k0 + k) * ldb + n0 + nq * 4);
        }
    };

    int KT = K / BK;
    load_tiles(0, 0);
    CP_COMMIT();
    for (int kt = 0; kt < KT; kt++) {
        if (kt + 1 < KT) load_tiles((kt + 1) & 1, (kt + 1) * BK);
        CP_COMMIT();
        CP_WAIT1();
        __syncthreads();
        int st = kt & 1;
        #pragma unroll
        for (int ks = 0; ks < 2; ks++) {
            int c = ks * 8 + tig;
            uint32_t afr[MT][4], bfr[NT][2];
            #pragma unroll
            for (int i = 0; i < MT; i++) {
                int r = wm * WTM + i * 16 + grp;
                afr[i][0] = f2tf(As[st][r][c]);
                afr[i][1] = f2tf(As[st][r + 8][c]);
                afr[i][2] = f2tf(As[st][r][c + 4]);
                afr[i][3] = f2tf(As[st][r + 8][c + 4]);
            }
            #pragma unroll
            for (int j = 0; j < NT; j++) {
                int nb = wn * WTN + j * 8 + grp;
                bfr[j][0] = f2tf(Bs[st][c][nb]);
                bfr[j][1] = f2tf(Bs[st][c + 4][nb]);
            }
            #pragma unroll
            for (int i = 0; i < MT; i++)
                #pragma unroll
                for (int j = 0; j < NT; j++)
                    mma8(acc[i][j], afr[i], bfr[j]);
        }
        __syncthreads();
    }

    #pragma unroll
    for (int i = 0; i < MT; i++) {
        #pragma unroll
        for (int half = 0; half < 2; half++) {
            int r = m0 + wm * WTM + i * 16 + grp + half * 8;
            #pragma unroll
            for (int j = 0; j < NT; j++) {
                int n = n0 + wn * WTN + j * 8 + tig * 2;
                *(float2*)(Cp + (size_t)r * ldc + n) =
                    make_float2(acc[i][j][half * 2 + 0], acc[i][j][half * 2 + 1]);
            }
        }
    }
}

// -------- patch embed + LN + pos: PGROW rows/CTA, parallel reductions --------
__global__ void __launch_bounds__(512)
k_patch(const float* __restrict__ x,
        const float* __restrict__ bng, const float* __restrict__ bnb,
        const float* __restrict__ bnm, const float* __restrict__ bnv,
        const float* __restrict__ pb,
        const float* __restrict__ lg,  const float* __restrict__ lb,
        const float* __restrict__ pos) {
    __shared__ float p[PGROW][KPATCH + 2];
    __shared__ float smS[PGROW][16], smQ[PGROW][16];
    __shared__ float smMV[PGROW][2];
    int row0 = blockIdx.x * PGROW, tid = threadIdx.x;
    int warp = tid >> 5, lane = tid & 31;

    for (int e = tid; e < PGROW * KPATCH; e += 512) {
        int g = e / KPATCH, k = e - g * KPATCH;
        int row = row0 + g;
        int b = row >> 4, l = row & 15;
        int c = k / PATCH, j = k - c * PATCH;
        float xv = x[(b * C_IN + c) * T_LEN + l * PATCH + j];
        p[g][k] = (xv - bnm[c]) * rsqrtf(bnv[c] + EPS) * bng[c] + bnb[c];
    }
    __syncthreads();

    float acc[PGROW];
    float bias = pb[tid];
    #pragma unroll
    for (int g = 0; g < PGROW; g++) acc[g] = bias;
    const float* wt = g_pwt + tid;
    #pragma unroll 2
    for (int k = 0; k < KPATCH; k++) {
        float w = wt[(size_t)k * D_MODEL];
        #pragma unroll
        for (int g = 0; g < PGROW; g++) acc[g] = fmaf(p[g][k], w, acc[g]);
    }

    // parallel sum+sumsq reductions for all PGROW rows (2 barriers total)
    #pragma unroll
    for (int g = 0; g < PGROW; g++) {
        float s = acc[g], q = acc[g] * acc[g];
        #pragma unroll
        for (int o = 16; o; o >>= 1) {
            s += __shfl_xor_sync(0xffffffffu, s, o);
            q += __shfl_xor_sync(0xffffffffu, q, o);
        }
        if (lane == 0) { smS[g][warp] = s; smQ[g][warp] = q; }
    }
    __syncthreads();
    if (warp < PGROW) {
        float s = (lane < 16) ? smS[warp][lane] : 0.f;
        float q = (lane < 16) ? smQ[warp][lane] : 0.f;
        #pragma unroll
        for (int o = 8; o; o >>= 1) {
            s += __shfl_xor_sync(0xffffffffu, s, o);
            q += __shfl_xor_sync(0xffffffffu, q, o);
        }
        if (lane == 0) {
            float mean = s * (1.f / D_MODEL);
            float var  = q * (1.f / D_MODEL) - mean * mean;
            smMV[warp][0] = mean;
            smMV[warp][1] = rsqrtf(var + EPS);
        }
    }
    __syncthreads();

    float gv = lg[tid], bv = lb[tid];
    #pragma unroll
    for (int g = 0; g < PGROW; g++) {
        int row = row0 + g;
        int l = row & 15;
        g_h[(size_t)row * D_MODEL + tid] =
            (acc[g] - smMV[g][0]) * smMV[g][1] * gv + bv + pos[l * D_MODEL + tid];
    }
}

// ---------------- LayerNorm: fp32 in -> bf16 out -----------------------------
__global__ void k_ln_bf(const float* __restrict__ in, __nv_bfloat16* __restrict__ out,
                        const float* __restrict__ g, const float* __restrict__ b) {
    __shared__ float sm[17];
    int row = blockIdx.x, tid = threadIdx.x;
    float v = in[row * D_MODEL + tid];
    float mean = block_sum_512(v, sm) * (1.f / D_MODEL);
    float df = v - mean;
    float var = block_sum_512(df * df, sm) * (1.f / D_MODEL);
    out[row * D_MODEL + tid] =
        __float2bfloat16(df * rsqrtf(var + EPS) * g[tid] + b[tid]);
}

// ---------------- LayerNorm: fp32 -> fp32 (final) ----------------------------
__global__ void k_ln(const float* __restrict__ in, float* __restrict__ out,
                     const float* __restrict__ g, const float* __restrict__ b) {
    __shared__ float sm[17];
    int row = blockIdx.x, tid = threadIdx.x;
    float v = in[row * D_MODEL + tid];
    float mean = block_sum_512(v, sm) * (1.f / D_MODEL);
    float df = v - mean;
    float var = block_sum_512(df * df, sm) * (1.f / D_MODEL);
    out[row * D_MODEL + tid] = df * rsqrtf(var + EPS) * g[tid] + b[tid];
}

// ---------------- causal depthwise conv + SiLU, both dirs -------------------
__global__ void k_conv(const float* __restrict__ cw, const float* __restrict__ cb) {
    int dir = blockIdx.z;
    int idx = blockIdx.x * 256 + threadIdx.x;
    int b = idx >> 10;
    int d = idx & (D_INNER - 1);
    const float* u = g_uz + (size_t)dir * M_ROWS * 2 * D_INNER
                   + (size_t)(b * L_TK) * (2 * D_INNER) + d;
    float* o = g_uc + (size_t)dir * M_ROWS * D_INNER
             + (size_t)(b * L_TK) * D_INNER + d;
    const float* cwd = cw + (size_t)dir * D_INNER * D_CONV;
    const float* cbd = cb + (size_t)dir * D_INNER;
    float w0 = cwd[d * D_CONV + 0], w1 = cwd[d * D_CONV + 1];
    float w2 = cwd[d * D_CONV + 2], w3 = cwd[d * D_CONV + 3];
    float bias = cbd[d];
    float h0 = 0.f, h1 = 0.f, h2 = 0.f;
    #pragma unroll
    for (int l = 0; l < L_TK; l++) {
        int j = dir ? (15 - l) : l;
        float cur = u[(size_t)j * (2 * D_INNER)];
        float a = bias;
        a = fmaf(w0, h0, a);
        a = fmaf(w1, h1, a);
        a = fmaf(w2, h2, a);
        a = fmaf(w3, cur, a);
        o[(size_t)l * D_INNER] = a / (1.f + __expf(-a));
        h0 = h1; h1 = h2; h2 = cur;
    }
}

// ---------------- fused dt_proj + softplus + scan + D skip + gate ------------
__global__ void k_scan(const float* __restrict__ Wdt, const float* __restrict__ bdt,
                       const float* __restrict__ Alog, const float* __restrict__ Dv) {
    __shared__ ull B2[L_TK][8], C2[L_TK][8];
    __shared__ float dtr[L_TK][DT_RANK];
    int dir = blockIdx.z;
    int b = blockIdx.x;
    int tid = threadIdx.x;
    int d = blockIdx.y * 256 + tid;

    const float* proj = g_proj + (size_t)dir * M_ROWS * PROJW;
    const float* ucp  = g_uc   + (size_t)dir * M_ROWS * D_INNER;
    const float* uzp  = g_uz   + (size_t)dir * M_ROWS * 2 * D_INNER;
    const float* Wdtd = Wdt  + (size_t)dir * DT_RANK * D_INNER;
    const float* bdtd = bdt  + (size_t)dir * D_INNER;
    const float* Al   = Alog + (size_t)dir * D_INNER * D_STATE;
    const float* Dp   = Dv   + (size_t)dir * D_INNER;

    for (int e = tid; e < L_TK * 8; e += 256) {
        int l = e >> 3, p = e & 7;
        const float* pr = proj + (size_t)(b * L_TK + l) * PROJW;
        float2 vb = *(const float2*)(pr + DT_RANK + p * 2);
        float2 vc = *(const float2*)(pr + DT_RANK + D_STATE + p * 2);
        B2[l][p] = pk2(vb.x, vb.y);
        C2[l][p] = pk2(vc.x, vc.y);
    }
    for (int e = tid; e < L_TK * DT_RANK; e += 256) {
        int l = e >> 5, k = e & 31;
        dtr[l][k] = proj[(size_t)(b * L_TK + l) * PROJW + k];
    }
    __syncthreads();

    float dtv[L_TK];
    {
        float bias = bdtd[d];
        #pragma unroll
        for (int l = 0; l < L_TK; l++) dtv[l] = bias;
        #pragma unroll 4
        for (int k = 0; k < DT_RANK; k++) {
            float w = Wdtd[(size_t)k * D_INNER + d];
            #pragma unroll
            for (int l = 0; l < L_TK; l++) dtv[l] = fmaf(dtr[l][k], w, dtv[l]);
        }
        #pragma unroll
        for (int l = 0; l < L_TK; l++) dtv[l] = softplusf(dtv[l]);
    }

    float A[D_STATE];
    bool ok = true;
    #pragma unroll
    for (int n = 0; n < D_STATE; n++) {
        A[n] = -__expf(Al[(size_t)d * D_STATE + n]);
        ok = ok && (fabsf(A[n] + (float)(n + 1)) < 2e-3f);
    }
    float Dd = Dp[d];

    if (ok) {
        ull st[8];
        #pragma unroll
        for (int p = 0; p < 8; p++) st[p] = pk2(0.f, 0.f);
        for (int l = 0; l < L_TK; l++) {
            int rp = b * L_TK + l;
            int rn = b * L_TK + (dir ? (15 - l) : l);
            float dt = dtv[l];
            float u  = ucp[(size_t)rp * D_INNER + d];
            float du = dt * u;
            float q  = __expf(-dt);
            float qq = q * q;
            ull w    = pk2(q, qq);
            ull step = pk2(qq, qq);
            ull du2  = pk2(du, du);
            ull y2   = pk2(0.f, 0.f);
            #pragma unroll
            for (int p = 0; p < 8; p++) {
                st[p] = fma2(st[p], w, mul2(du2, B2[l][p]));
                y2 = fma2(st[p], C2[l][p], y2);
                w = mul2(w, step);
            }
            float ylo, yhi;
            upk2(y2, ylo, yhi);
            float y = ylo + yhi + u * Dd;
            float zv = uzp[(size_t)rn * (2 * D_INNER) + D_INNER + d];
            g_ysb[(size_t)rn * (2 * D_INNER) + dir * D_INNER + d] =
                __float2bfloat16(y * (zv / (1.f + __expf(-zv))));
        }
    } else {
        float st[D_STATE];
        #pragma unroll
        for (int n = 0; n < D_STATE; n++) st[n] = 0.f;
        for (int l = 0; l < L_TK; l++) {
            int rp = b * L_TK + l;
            int rn = b * L_TK + (dir ? (15 - l) : l);
            float dt = dtv[l];
            float u  = ucp[(size_t)rp * D_INNER + d];
            float du = dt * u;
            float y = 0.f;
            #pragma unroll
            for (int n = 0; n < D_STATE; n++) {
                float blo, bhi, clo, chi;
                upk2(B2[l][n >> 1], blo, bhi);
                upk2(C2[l][n >> 1], clo, chi);
                float Bv = (n & 1) ? bhi : blo;
                float Cv = (n & 1) ? chi : clo;
                float s = fmaf(st[n], __expf(dt * A[n]), du * Bv);
                st[n] = s;
                y = fmaf(s, Cv, y);
            }
            y = fmaf(u, Dd, y);
            float zv = uzp[(size_t)rn * (2 * D_INNER) + D_INNER + d];
            g_ysb[(size_t)rn * (2 * D_INNER) + dir * D_INNER + d] =
                __float2bfloat16(y * (zv / (1.f + __expf(-zv))));
        }
    }
}

// ---------------- launch -----------------------------------------------------
extern "C" void kernel_launch(void* const* d_in, const int* in_sizes, int n_in,
                              void* d_out, int out_size) {
    const float* x    = (const float*)d_in[0];
    const float* bng  = (const float*)d_in[1];
    const float* bnb  = (const float*)d_in[2];
    const float* bnm  = (const float*)d_in[3];
    const float* bnv  = (const float*)d_in[4];
    const float* pw   = (const float*)d_in[5];
    const float* pb   = (const float*)d_in[6];
    const float* lpg  = (const float*)d_in[7];
    const float* lpb  = (const float*)d_in[8];
    const float* pos  = (const float*)d_in[9];
    const float* blg  = (const float*)d_in[10];
    const float* blb  = (const float*)d_in[11];
    const float* Wi   = (const float*)d_in[12];
    const float* cw   = (const float*)d_in[13];
    const float* cb   = (const float*)d_in[14];
    const float* Wx   = (const float*)d_in[15];
    const float* Wdt  = (const float*)d_in[16];
    const float* bdt  = (const float*)d_in[17];
    const float* Alog = (const float*)d_in[18];
    const float* Dv   = (const float*)d_in[19];
    const float* Wo   = (const float*)d_in[20];
    const float* flg  = (const float*)d_in[21];
    const float* flb  = (const float*)d_in[22];
    float* out = (float*)d_out;

    float *ph, *puz, *puc, *pproj, *ppwt;
    __nv_bfloat16 *phnb, *pysb, *pwib, *pwob;
    cudaGetSymbolAddress((void**)&ph,   g_h);
    cudaGetSymbolAddress((void**)&puz,  g_uz);
    cudaGetSymbolAddress((void**)&puc,  g_uc);
    cudaGetSymbolAddress((void**)&pproj,g_proj);
    cudaGetSymbolAddress((void**)&ppwt, g_pwt);
    cudaGetSymbolAddress((void**)&phnb, g_hnb);
    cudaGetSymbolAddress((void**)&pysb, g_ysb);
    cudaGetSymbolAddress((void**)&pwib, g_wib);
    cudaGetSymbolAddress((void**)&pwob, g_wob);

    static int attr_done = 0;
    if (!attr_done) {
        cudaFuncSetAttribute(k_mmab<128,128,2,4,0>,
                             cudaFuncAttributeMaxDynamicSharedMemorySize, MMAB_SMEM);
        cudaFuncSetAttribute(k_mmab<64,128,2,4,2>,
                             cudaFuncAttributeMaxDynamicSharedMemorySize, MMAB_SMEM64);
        attr_done = 1;
    }

    // weight transpose-convert
    k_tb<<<dim3(2 * D_INNER / 32, D_MODEL / 32, 4), dim3(32, 8)>>>(
        Wi, pwib, D_MODEL, 2 * D_INNER);
    k_tb<<<dim3(D_MODEL / 32, 2 * D_INNER / 32, 2), dim3(32, 8)>>>(
        Wo, pwob, 2 * D_INNER, D_MODEL);
    k_tpw<<<KPATCH, D_MODEL>>>(pw, ppwt);

    k_patch<<<M_ROWS / PGROW, 512>>>(x, bng, bnb, bnm, bnv, pb, lpg, lpb, pos);

    for (int i = 0; i < 2; i++) {
        k_ln_bf<<<M_ROWS, 512>>>(ph, phnb, blg + i * D_MODEL, blb + i * D_MODEL);

        // in_proj both dirs: bf16 (4096,512)@(512,2048) -> g_uz[dir]
        k_mmab<128,128,2,4,0>
            <<<dim3(2 * D_INNER / 128, M_ROWS / 128, 2), 256, MMAB_SMEM>>>(
            phnb, D_MODEL, 0,
            pwib + (size_t)i * 2 * 2 * D_INNER * D_MODEL, D_MODEL,
            (long)2 * D_INNER * D_MODEL,
            puz, 2 * D_INNER, (long)M_ROWS * 2 * D_INNER,
            D_MODEL);

        // conv + SiLU both dirs
        k_conv<<<dim3((B_SZ * D_INNER) / 256, 1, 2), 256>>>(
            cw + (size_t)i * 2 * D_INNER * D_CONV, cb + (size_t)i * 2 * D_INNER);

        // x_proj both dirs: tf32 (4096,1024)@(1024,64) -> g_proj[dir]
        k_mma<64,64,2,2><<<dim3(1, M_ROWS / 64, 2), 128>>>(
            puc, D_INNER, (long)M_ROWS * D_INNER,
            Wx + (size_t)i * 2 * D_INNER * PROJW, PROJW, (long)D_INNER * PROJW,
            pproj, PROJW, (long)M_ROWS * PROJW,
            D_INNER);

        // fused dt_proj + scan both dirs -> g_ysb (bf16)
        k_scan<<<dim3(B_SZ, D_INNER / 256, 2), 256>>>(
            Wdt  + (size_t)i * 2 * DT_RANK * D_INNER,
            bdt  + (size_t)i * 2 * D_INNER,
            Alog + (size_t)i * 2 * D_INNER * D_STATE,
            Dv   + (size_t)i * 2 * D_INNER);

        // out_proj: bf16 (4096,2048)@(2048,512) += g_h  [BM=64 -> 256 CTAs]
        k_mmab<64,128,2,4,2>
            <<<dim3(D_MODEL / 128, M_ROWS / 64, 1), 256, MMAB_SMEM64>>>(
            pysb, 2 * D_INNER, 0,
            pwob + (size_t)i * 2 * D_INNER * D_MODEL, 2 * D_INNER, 0,
            ph, D_MODEL, 0,
            2 * D_INNER);
    }
    k_ln<<<M_ROWS, 512>>>(ph, out, flg, flb);
}

// round 16
// speedup vs baseline: 1.7025x; 1.0039x over previous
#include <cuda_runtime.h>
#include <cuda_bf16.h>
#include <math.h>
#include <stdint.h>

#define B_SZ   256
#define C_IN   7
#define T_LEN  160
#define PATCH  10
#define L_TK   16
#define D_MODEL 512
#define D_INNER 1024
#define D_STATE 16
#define DT_RANK 32
#define D_CONV  4
#define M_ROWS (B_SZ * L_TK)          // 4096
#define PROJW  (DT_RANK + 2*D_STATE)  // 64
#define KPATCH (C_IN * PATCH)         // 70
#define PGROW  8                      // rows per patch CTA
#define EPS 1e-5f

// ---------------- scratch ----------------------------------------------------
__device__ float g_h  [M_ROWS * D_MODEL];
__device__ float g_uz [2 * M_ROWS * 2 * D_INNER];
__device__ float g_uc [2 * M_ROWS * D_INNER];
__device__ float g_proj[2 * M_ROWS * PROJW];
__device__ float g_pwt[KPATCH * D_MODEL];                    // transposed patch_w
__device__ __nv_bfloat16 g_hnb[M_ROWS * D_MODEL];
__device__ __nv_bfloat16 g_ysb[M_ROWS * 2 * D_INNER];        // [row][dir*1024+d]
__device__ __nv_bfloat16 g_wib[4 * 2 * D_INNER * D_MODEL];   // 4 x [2048][512]
__device__ __nv_bfloat16 g_wob[2 * 2 * D_INNER * D_MODEL];   // 2 x [512][2048]

// ---------------- helpers ----------------------------------------------------
__device__ __forceinline__ uint32_t f2tf(float x) {
    uint32_t r; asm("cvt.rna.tf32.f32 %0, %1;" : "=r"(r) : "f"(x)); return r;
}
__device__ __forceinline__ void mma8(float* c, const uint32_t* a, const uint32_t* b) {
    asm volatile(
        "mma.sync.aligned.m16n8k8.row.col.f32.tf32.tf32.f32 "
        "{%0,%1,%2,%3},{%4,%5,%6,%7},{%8,%9},{%0,%1,%2,%3};"
        : "+f"(c[0]), "+f"(c[1]), "+f"(c[2]), "+f"(c[3])
        : "r"(a[0]), "r"(a[1]), "r"(a[2]), "r"(a[3]), "r"(b[0]), "r"(b[1]));
}
__device__ __forceinline__ void mma16(float* c, const uint32_t* a, const uint32_t* b) {
    asm volatile(
        "mma.sync.aligned.m16n8k16.row.col.f32.bf16.bf16.f32 "
        "{%0,%1,%2,%3},{%4,%5,%6,%7},{%8,%9},{%0,%1,%2,%3};"
        : "+f"(c[0]), "+f"(c[1]), "+f"(c[2]), "+f"(c[3])
        : "r"(a[0]), "r"(a[1]), "r"(a[2]), "r"(a[3]), "r"(b[0]), "r"(b[1]));
}
__device__ __forceinline__ void ldsm4(uint32_t& r0, uint32_t& r1, uint32_t& r2,
                                      uint32_t& r3, uint32_t addr) {
    asm volatile("ldmatrix.sync.aligned.m8n8.x4.shared.b16 {%0,%1,%2,%3}, [%4];"
                 : "=r"(r0), "=r"(r1), "=r"(r2), "=r"(r3) : "r"(addr));
}
__device__ __forceinline__ float softplusf(float v) {
    return fmaxf(v, 0.f) + log1pf(__expf(-fabsf(v)));
}
__device__ __forceinline__ void cp16(void* dst, const void* src) {
    uint32_t d = (uint32_t)__cvta_generic_to_shared(dst);
    asm volatile("cp.async.cg.shared.global [%0], [%1], 16;" :: "r"(d), "l"(src));
}
#define CP_COMMIT() asm volatile("cp.async.commit_group;")
#define CP_WAIT1()  asm volatile("cp.async.wait_group 1;")
#define CP_WAIT2()  asm volatile("cp.async.wait_group 2;")

typedef unsigned long long ull;
__device__ __forceinline__ ull pk2(float x, float y) {
    ull r; asm("mov.b64 %0, {%1,%2};" : "=l"(r) : "f"(x), "f"(y)); return r;
}
__device__ __forceinline__ void upk2(ull v, float& x, float& y) {
    asm("mov.b64 {%0,%1}, %2;" : "=f"(x), "=f"(y) : "l"(v));
}
__device__ __forceinline__ ull fma2(ull a, ull b, ull c) {
    ull d; asm("fma.rn.f32x2 %0, %1, %2, %3;" : "=l"(d) : "l"(a), "l"(b), "l"(c)); return d;
}
__device__ __forceinline__ ull mul2(ull a, ull b) {
    ull d; asm("mul.rn.f32x2 %0, %1, %2;" : "=l"(d) : "l"(a), "l"(b)); return d;
}

// fused mean/rstd for one 512-wide row, 2 barriers
__device__ __forceinline__ void ln_stats_512(float v, float* smS, float* smQ,
                                             float* smMV, float& mean, float& rstd) {
    int tid = threadIdx.x, warp = tid >> 5, lane = tid & 31;
    float s = v, q = v * v;
    #pragma unroll
    for (int o = 16; o; o >>= 1) {
        s += __shfl_xor_sync(0xffffffffu, s, o);
        q += __shfl_xor_sync(0xffffffffu, q, o);
    }
    if (lane == 0) { smS[warp] = s; smQ[warp] = q; }
    __syncthreads();
    if (warp == 0) {
        float s2 = (lane < 16) ? smS[lane] : 0.f;
        float q2 = (lane < 16) ? smQ[lane] : 0.f;
        #pragma unroll
        for (int o = 8; o; o >>= 1) {
            s2 += __shfl_xor_sync(0xffffffffu, s2, o);
            q2 += __shfl_xor_sync(0xffffffffu, q2, o);
        }
        if (lane == 0) {
            float m = s2 * (1.f / D_MODEL);
            float var = q2 * (1.f / D_MODEL) - m * m;
            smMV[0] = m;
            smMV[1] = rsqrtf(var + EPS);
        }
    }
    __syncthreads();
    mean = smMV[0];
    rstd = smMV[1];
}

// ---------------- transpose + convert weights to bf16 ------------------------
__global__ void k_tb(const float* __restrict__ src, __nv_bfloat16* __restrict__ dst,
                     int K, int N) {
    __shared__ __nv_bfloat16 t[32][33];
    long zo = (long)blockIdx.z * K * N;
    int n0 = blockIdx.x * 32, k0 = blockIdx.y * 32;
    for (int i = threadIdx.y; i < 32; i += 8)
        t[i][threadIdx.x] = __float2bfloat16(src[zo + (size_t)(k0 + i) * N + n0 + threadIdx.x]);
    __syncthreads();
    for (int i = threadIdx.y; i < 32; i += 8)
        dst[zo + (size_t)(n0 + i) * K + k0 + threadIdx.x] = t[threadIdx.x][i];
}

// ---------------- transpose patch_w [512][70] -> [70][512] -------------------
__global__ void k_tpw(const float* __restrict__ src, float* __restrict__ dst) {
    int k = blockIdx.x;                // 0..69
    int n = threadIdx.x;               // 0..511
    dst[k * D_MODEL + n] = src[(size_t)n * KPATCH + k];
}

// ---------------- 3-stage bf16 MMA GEMM with ldmatrix ------------------------
// A [M][K] bf16 row-major, B [N][K] bf16 row-major (pre-transposed weights).
// EPI: 0 = store fp32, 2 = accumulate fp32. Dynamic smem (3 stages).
template<int BM, int BN, int WARPS_M, int WARPS_N, int EPI>
__global__ void __launch_bounds__(WARPS_M * WARPS_N * 32)
k_mmab(const __nv_bfloat16* __restrict__ A, int lda, long strideAz,
       const __nv_bfloat16* __restrict__ Bg, int ldb, long strideBz,
       float* __restrict__ C, int ldc, long strideCz, int K) {
    constexpr int BK = 32;
    constexpr int LDP = 20;               // 80B row stride: 16B aligned, conflict-free
    constexpr int NS  = 3;
    constexpr int T  = WARPS_M * WARPS_N * 32;
    constexpr int WTM = BM / WARPS_M;
    constexpr int WTN = BN / WARPS_N;
    constexpr int MT  = WTM / 16;
    constexpr int NT  = WTN / 8;
    static_assert(NT % 2 == 0, "NT must be even for paired B ldmatrix");

    extern __shared__ uint32_t dyn[];
    typedef uint32_t ATile[BM][LDP];
    typedef uint32_t BTile[BN][LDP];
    ATile* As2 = (ATile*)dyn;
    BTile* Bs2 = (BTile*)(dyn + NS * BM * LDP);

    int tid = threadIdx.x, lane = tid & 31, wid = tid >> 5;
    int wm = wid % WARPS_M, wn = wid / WARPS_M;
    int m0 = blockIdx.y * BM, n0 = blockIdx.x * BN;
    int z = blockIdx.z;
    int tig = lane & 3, grp = lane >> 2;

    const __nv_bfloat16* Ap = A + (long)z * strideAz;
    const __nv_bfloat16* Bp = Bg + (long)z * strideBz;
    float* Cp = C + (long)z * strideCz;

    int a_row_off = (lane & 7) + ((lane >> 3) & 1) * 8;
    int a_col_off = ((lane >> 4) & 1) * 4;
    int b_row_off = (lane & 7) + ((lane >> 4) & 1) * 8;
    int b_col_off = ((lane >> 3) & 1) * 4;

    float acc[MT][NT][4];
    #pragma unroll
    for (int i = 0; i < MT; i++)
        #pragma unroll
        for (int j = 0; j < NT; j++)
            #pragma unroll
            for (int q = 0; q < 4; q++) acc[i][j][q] = 0.f;

    auto load_tiles = [&](int st, int k0) {
        #pragma unroll 2
        for (int idx = tid; idx < BM * 4; idx += T) {
            int m = idx >> 2, c = idx & 3;
            cp16(&As2[st][m][c * 4], Ap + (size_t)(m0 + m) * lda + k0 + c * 8);
        }
        #pragma unroll 2
        for (int idx = tid; idx < BN * 4; idx += T) {
            int n = idx >> 2, c = idx & 3;
            cp16(&Bs2[st][n][c * 4], Bp + (size_t)(n0 + n) * ldb + k0 + c * 8);
        }
    };

    int KT = K / BK;
    load_tiles(0, 0);
    CP_COMMIT();
    load_tiles(1, BK);
    CP_COMMIT();
    int st = 0;
    for (int kt = 0; kt < KT; kt++) {
        if (kt + 2 < KT) {
            int s2 = st + 2; if (s2 >= NS) s2 -= NS;
            load_tiles(s2, (kt + 2) * BK);
        }
        CP_COMMIT();
        CP_WAIT2();
        __syncthreads();

        uint32_t aBase = (uint32_t)__cvta_generic_to_shared(&As2[st][0][0]);
        uint32_t bBase = (uint32_t)__cvta_generic_to_shared(&Bs2[st][0][0]);
        #pragma unroll
        for (int ks = 0; ks < 2; ks++) {
            int pb = ks * 8;
            uint32_t afr[MT][4], bfr[NT][2];
            #pragma unroll
            for (int i = 0; i < MT; i++) {
                int r = wm * WTM + i * 16;
                uint32_t addr = aBase +
                    (uint32_t)(((r + a_row_off) * LDP + pb + a_col_off) * 4);
                ldsm4(afr[i][0], afr[i][1], afr[i][2], afr[i][3], addr);
            }
            #pragma unroll
            for (int j = 0; j < NT; j += 2) {
                int nb = wn * WTN + j * 8;
                uint32_t addr = bBase +
                    (uint32_t)(((nb + b_row_off) * LDP + pb + b_col_off) * 4);
                ldsm4(bfr[j][0], bfr[j][1], bfr[j + 1][0], bfr[j + 1][1], addr);
            }
            #pragma unroll
            for (int i = 0; i < MT; i++)
                #pragma unroll
                for (int j = 0; j < NT; j++)
                    mma16(acc[i][j], afr[i], bfr[j]);
        }
        __syncthreads();
        if (++st >= NS) st = 0;
    }

    #pragma unroll
    for (int i = 0; i < MT; i++) {
        #pragma unroll
        for (int half = 0; half < 2; half++) {
            int r = m0 + wm * WTM + i * 16 + grp + half * 8;
            #pragma unroll
            for (int j = 0; j < NT; j++) {
                int n = n0 + wn * WTN + j * 8 + tig * 2;
                float v0 = acc[i][j][half * 2 + 0];
                float v1 = acc[i][j][half * 2 + 1];
                float* cp = Cp + (size_t)r * ldc + n;
                if (EPI == 2) {
                    cp[0] += v0;
                    cp[1] += v1;
                } else {
                    *(float2*)cp = make_float2(v0, v1);
                }
            }
        }
    }
}
#define MMAB_SMEM (3 * (128 * 20 + 128 * 20) * 4)

// ---------------- tf32 MMA GEMM (x_proj) -------------------------------------
template<int BM, int BN, int WARPS_M, int WARPS_N>
__global__ void __launch_bounds__(WARPS_M * WARPS_N * 32)
k_mma(const float* __restrict__ A, int lda, long strideAz,
      const float* __restrict__ Bg, int ldb, long strideBz,
      float* __restrict__ C, int ldc, long strideCz, int K) {
    constexpr int BK = 16;
    constexpr int T  = WARPS_M * WARPS_N * 32;
    constexpr int WTM = BM / WARPS_M;
    constexpr int WTN = BN / WARPS_N;
    constexpr int MT  = WTM / 16;
    constexpr int NT  = WTN / 8;

    __shared__ float As[2][BM][BK + 4];
    __shared__ float Bs[2][BK][BN + 8];

    int tid = threadIdx.x, lane = tid & 31, wid = tid >> 5;
    int wm = wid % WARPS_M, wn = wid / WARPS_M;
    int m0 = blockIdx.y * BM, n0 = blockIdx.x * BN;
    int z = blockIdx.z;
    int tig = lane & 3, grp = lane >> 2;

    const float* Ap = A + (long)z * strideAz;
    const float* Bp = Bg + (long)z * strideBz;
    float* Cp = C + (long)z * strideCz;

    float acc[MT][NT][4];
    #pragma unroll
    for (int i = 0; i < MT; i++)
        #pragma unroll
        for (int j = 0; j < NT; j++)
            #pragma unroll
            for (int q = 0; q < 4; q++) acc[i][j][q] = 0.f;

    auto load_tiles = [&](int st, int k0) {
        #pragma unroll 2
        for (int idx = tid; idx < BM * 4; idx += T) {
            int m = idx >> 2, kq = idx & 3;
            cp16(&As[st][m][kq * 4], Ap + (size_t)(m0 + m) * lda + k0 + kq * 4);
        }
        #pragma unroll 2
        for (int idx = tid; idx < BK * BN / 4; idx += T) {
            int k = idx / (BN / 4), nq = idx % (BN / 4);
            cp16(&Bs[st][k][nq * 4], Bp + (size_t)(k0 + k) * ldb + n0 + nq * 4);
        }
    };

    int KT = K / BK;
    load_tiles(0, 0);
    CP_COMMIT();
    for (int kt = 0; kt < KT; kt++) {
        if (kt + 1 < KT) load_tiles((kt + 1) & 1, (kt + 1) * BK);
        CP_COMMIT();
        CP_WAIT1();
        __syncthreads();
        int st = kt & 1;
        #pragma unroll
        for (int ks = 0; ks < 2; ks++) {
            int c = ks * 8 + tig;
            uint32_t afr[MT][4], bfr[NT][2];
            #pragma unroll
            for (int i = 0; i < MT; i++) {
                int r = wm * WTM + i * 16 + grp;
                afr[i][0] = f2tf(As[st][r][c]);
                afr[i][1] = f2tf(As[st][r + 8][c]);
                afr[i][2] = f2tf(As[st][r][c + 4]);
                afr[i][3] = f2tf(As[st][r + 8][c + 4]);
            }
            #pragma unroll
            for (int j = 0; j < NT; j++) {
                int nb = wn * WTN + j * 8 + grp;
                bfr[j][0] = f2tf(Bs[st][c][nb]);
                bfr[j][1] = f2tf(Bs[st][c + 4][nb]);
            }
            #pragma unroll
            for (int i = 0; i < MT; i++)
                #pragma unroll
                for (int j = 0; j < NT; j++)
                    mma8(acc[i][j], afr[i], bfr[j]);
        }
        __syncthreads();
    }

    #pragma unroll
    for (int i = 0; i < MT; i++) {
        #pragma unroll
        for (int half = 0; half < 2; half++) {
            int r = m0 + wm * WTM + i * 16 + grp + half * 8;
            #pragma unroll
            for (int j = 0; j < NT; j++) {
                int n = n0 + wn * WTN + j * 8 + tig * 2;
                *(float2*)(Cp + (size_t)r * ldc + n) =
                    make_float2(acc[i][j][half * 2 + 0], acc[i][j][half * 2 + 1]);
            }
        }
    }
}

// -------- patch embed + LN + pos: PGROW rows/CTA, parallel reductions --------
__global__ void __launch_bounds__(512)
k_patch(const float* __restrict__ x,
        const float* __restrict__ bng, const float* __restrict__ bnb,
        const float* __restrict__ bnm, const float* __restrict__ bnv,
        const float* __restrict__ pb,
        const float* __restrict__ lg,  const float* __restrict__ lb,
        const float* __restrict__ pos) {
    __shared__ float p[PGROW][KPATCH + 2];
    __shared__ float smS[PGROW][16], smQ[PGROW][16];
    __shared__ float smMV[PGROW][2];
    int row0 = blockIdx.x * PGROW, tid = threadIdx.x;
    int warp = tid >> 5, lane = tid & 31;

    for (int e = tid; e < PGROW * KPATCH; e += 512) {
        int g = e / KPATCH, k = e - g * KPATCH;
        int row = row0 + g;
        int b = row >> 4, l = row & 15;
        int c = k / PATCH, j = k - c * PATCH;
        float xv = x[(b * C_IN + c) * T_LEN + l * PATCH + j];
        p[g][k] = (xv - bnm[c]) * rsqrtf(bnv[c] + EPS) * bng[c] + bnb[c];
    }
    __syncthreads();

    float acc[PGROW];
    float bias = pb[tid];
    #pragma unroll
    for (int g = 0; g < PGROW; g++) acc[g] = bias;
    const float* wt = g_pwt + tid;
    #pragma unroll 2
    for (int k = 0; k < KPATCH; k++) {
        float w = wt[(size_t)k * D_MODEL];
        #pragma unroll
        for (int g = 0; g < PGROW; g++) acc[g] = fmaf(p[g][k], w, acc[g]);
    }

    #pragma unroll
    for (int g = 0; g < PGROW; g++) {
        float s = acc[g], q = acc[g] * acc[g];
        #pragma unroll
        for (int o = 16; o; o >>= 1) {
            s += __shfl_xor_sync(0xffffffffu, s, o);
            q += __shfl_xor_sync(0xffffffffu, q, o);
        }
        if (lane == 0) { smS[g][warp] = s; smQ[g][warp] = q; }
    }
    __syncthreads();
    if (warp < PGROW) {
        float s = (lane < 16) ? smS[warp][lane] : 0.f;
        float q = (lane < 16) ? smQ[warp][lane] : 0.f;
        #pragma unroll
        for (int o = 8; o; o >>= 1) {
            s += __shfl_xor_sync(0xffffffffu, s, o);
            q += __shfl_xor_sync(0xffffffffu, q, o);
        }
        if (lane == 0) {
            float mean = s * (1.f / D_MODEL);
            float var  = q * (1.f / D_MODEL) - mean * mean;
            smMV[warp][0] = mean;
            smMV[warp][1] = rsqrtf(var + EPS);
        }
    }
    __syncthreads();

    float gv = lg[tid], bv = lb[tid];
    #pragma unroll
    for (int g = 0; g < PGROW; g++) {
        int row = row0 + g;
        int l = row & 15;
        g_h[(size_t)row * D_MODEL + tid] =
            (acc[g] - smMV[g][0]) * smMV[g][1] * gv + bv + pos[l * D_MODEL + tid];
    }
}

// ---------------- LayerNorm: fp32 in -> bf16 out (2 barriers) ----------------
__global__ void k_ln_bf(const float* __restrict__ in, __nv_bfloat16* __restrict__ out,
                        const float* __restrict__ g, const float* __restrict__ b) {
    __shared__ float smS[16], smQ[16], smMV[2];
    int row = blockIdx.x, tid = threadIdx.x;
    float v = in[row * D_MODEL + tid];
    float mean, rstd;
    ln_stats_512(v, smS, smQ, smMV, mean, rstd);
    out[row * D_MODEL + tid] =
        __float2bfloat16((v - mean) * rstd * g[tid] + b[tid]);
}

// ---------------- LayerNorm: fp32 -> fp32 (final, 2 barriers) ----------------
__global__ void k_ln(const float* __restrict__ in, float* __restrict__ out,
                     const float* __restrict__ g, const float* __restrict__ b) {
    __shared__ float smS[16], smQ[16], smMV[2];
    int row = blockIdx.x, tid = threadIdx.x;
    float v = in[row * D_MODEL + tid];
    float mean, rstd;
    ln_stats_512(v, smS, smQ, smMV, mean, rstd);
    out[row * D_MODEL + tid] = (v - mean) * rstd * g[tid] + b[tid];
}

// ------- causal depthwise conv + SiLU, both dirs, float4 over d --------------
__global__ void __launch_bounds__(256)
k_conv(const float* __restrict__ cw, const float* __restrict__ cb) {
    int dir = blockIdx.z;
    int idx = blockIdx.x * 256 + threadIdx.x;    // B_SZ * (D_INNER/4)
    int b = idx >> 8;
    int d = (idx & 255) * 4;
    const float4* u = (const float4*)(g_uz + (size_t)dir * M_ROWS * 2 * D_INNER
                                      + (size_t)(b * L_TK) * (2 * D_INNER) + d);
    float4* o = (float4*)(g_uc + (size_t)dir * M_ROWS * D_INNER
                          + (size_t)(b * L_TK) * D_INNER + d);
    const float* cwd = cw + (size_t)dir * D_INNER * D_CONV;
    const float* cbd = cb + (size_t)dir * D_INNER;
    float4 w0 = *(const float4*)(cwd + (d + 0) * D_CONV);
    float4 w1 = *(const float4*)(cwd + (d + 1) * D_CONV);
    float4 w2 = *(const float4*)(cwd + (d + 2) * D_CONV);
    float4 w3 = *(const float4*)(cwd + (d + 3) * D_CONV);
    float4 bias = *(const float4*)(cbd + d);
    float4 h0 = make_float4(0.f, 0.f, 0.f, 0.f);
    float4 h1 = h0, h2 = h0;
    #pragma unroll
    for (int l = 0; l < L_TK; l++) {
        int j = dir ? (15 - l) : l;
        float4 cur = u[(size_t)j * (2 * D_INNER / 4)];
        float a0 = bias.x, a1 = bias.y, a2 = bias.z, a3 = bias.w;
        a0 = fmaf(w0.x, h0.x, a0); a0 = fmaf(w0.y, h1.x, a0);
        a0 = fmaf(w0.z, h2.x, a0); a0 = fmaf(w0.w, cur.x, a0);
        a1 = fmaf(w1.x, h0.y, a1); a1 = fmaf(w1.y, h1.y, a1);
        a1 = fmaf(w1.z, h2.y, a1); a1 = fmaf(w1.w, cur.y, a1);
        a2 = fmaf(w2.x, h0.z, a2); a2 = fmaf(w2.y, h1.z, a2);
        a2 = fmaf(w2.z, h2.z, a2); a2 = fmaf(w2.w, cur.z, a2);
        a3 = fmaf(w3.x, h0.w, a3); a3 = fmaf(w3.y, h1.w, a3);
        a3 = fmaf(w3.z, h2.w, a3); a3 = fmaf(w3.w, cur.w, a3);
        float4 r;
        r.x = a0 / (1.f + __expf(-a0));
        r.y = a1 / (1.f + __expf(-a1));
        r.z = a2 / (1.f + __expf(-a2));
        r.w = a3 / (1.f + __expf(-a3));
        o[(size_t)l * (D_INNER / 4)] = r;
        h0 = h1; h1 = h2; h2 = cur;
    }
}

// ---------------- fused dt_proj + softplus + scan + D skip + gate ------------
__global__ void k_scan(const float* __restrict__ Wdt, const float* __restrict__ bdt,
                       const float* __restrict__ Alog, const float* __restrict__ Dv) {
    __shared__ ull B2[L_TK][8], C2[L_TK][8];
    __shared__ float dtr[L_TK][DT_RANK];
    int dir = blockIdx.z;
    int b = blockIdx.x;
    int tid = threadIdx.x;
    int d = blockIdx.y * 256 + tid;

    const float* proj = g_proj + (size_t)dir * M_ROWS * PROJW;
    const float* ucp  = g_uc   + (size_t)dir * M_ROWS * D_INNER;
    const float* uzp  = g_uz   + (size_t)dir * M_ROWS * 2 * D_INNER;
    const float* Wdtd = Wdt  + (size_t)dir * DT_RANK * D_INNER;
    const float* bdtd = bdt  + (size_t)dir * D_INNER;
    const float* Al   = Alog + (size_t)dir * D_INNER * D_STATE;
    const float* Dp   = Dv   + (size_t)dir * D_INNER;

    for (int e = tid; e < L_TK * 8; e += 256) {
        int l = e >> 3, p = e & 7;
        const float* pr = proj + (size_t)(b * L_TK + l) * PROJW;
        float2 vb = *(const float2*)(pr + DT_RANK + p * 2);
        float2 vc = *(const float2*)(pr + DT_RANK + D_STATE + p * 2);
        B2[l][p] = pk2(vb.x, vb.y);
        C2[l][p] = pk2(vc.x, vc.y);
    }
    for (int e = tid; e < L_TK * DT_RANK; e += 256) {
        int l = e >> 5, k = e & 31;
        dtr[l][k] = proj[(size_t)(b * L_TK + l) * PROJW + k];
    }
    __syncthreads();

    float dtv[L_TK];
    {
        float bias = bdtd[d];
        #pragma unroll
        for (int l = 0; l < L_TK; l++) dtv[l] = bias;
        #pragma unroll 4
        for (int k = 0; k < DT_RANK; k++) {
            float w = Wdtd[(size_t)k * D_INNER + d];
            #pragma unroll
            for (int l = 0; l < L_TK; l++) dtv[l] = fmaf(dtr[l][k], w, dtv[l]);
        }
        #pragma unroll
        for (int l = 0; l < L_TK; l++) dtv[l] = softplusf(dtv[l]);
    }

    float A[D_STATE];
    bool ok = true;
    #pragma unroll
    for (int n = 0; n < D_STATE; n++) {
        A[n] = -__expf(Al[(size_t)d * D_STATE + n]);
        ok = ok && (fabsf(A[n] + (float)(n + 1)) < 2e-3f);
    }
    float Dd = Dp[d];

    if (ok) {
        ull st[8];
        #pragma unroll
        for (int p = 0; p < 8; p++) st[p] = pk2(0.f, 0.f);
        for (int l = 0; l < L_TK; l++) {
            int rp = b * L_TK + l;
            int rn = b * L_TK + (dir ? (15 - l) : l);
            float dt = dtv[l];
            float u  = ucp[(size_t)rp * D_INNER + d];
            float du = dt * u;
            float q  = __expf(-dt);
            float qq = q * q;
            ull w    = pk2(q, qq);
            ull step = pk2(qq, qq);
            ull du2  = pk2(du, du);
            ull y2   = pk2(0.f, 0.f);
            #pragma unroll
            for (int p = 0; p < 8; p++) {
                st[p] = fma2(st[p], w, mul2(du2, B2[l][p]));
                y2 = fma2(st[p], C2[l][p], y2);
                w = mul2(w, step);
            }
            float ylo, yhi;
            upk2(y2, ylo, yhi);
            float y = ylo + yhi + u * Dd;
            float zv = uzp[(size_t)rn * (2 * D_INNER) + D_INNER + d];
            g_ysb[(size_t)rn * (2 * D_INNER) + dir * D_INNER + d] =
                __float2bfloat16(y * (zv / (1.f + __expf(-zv))));
        }
    } else {
        float st[D_STATE];
        #pragma unroll
        for (int n = 0; n < D_STATE; n++) st[n] = 0.f;
        for (int l = 0; l < L_TK; l++) {
            int rp = b * L_TK + l;
            int rn = b * L_TK + (dir ? (15 - l) : l);
            float dt = dtv[l];
            float u  = ucp[(size_t)rp * D_INNER + d];
            float du = dt * u;
            float y = 0.f;
            #pragma unroll
            for (int n = 0; n < D_STATE; n++) {
                float blo, bhi, clo, chi;
                upk2(B2[l][n >> 1], blo, bhi);
                upk2(C2[l][n >> 1], clo, chi);
                float Bv = (n & 1) ? bhi : blo;
                float Cv = (n & 1) ? chi : clo;
                float s = fmaf(st[n], __expf(dt * A[n]), du * Bv);
                st[n] = s;
                y = fmaf(s, Cv, y);
            }
            y = fmaf(u, Dd, y);
            float zv = uzp[(size_t)rn * (2 * D_INNER) + D_INNER + d];
            g_ysb[(size_t)rn * (2 * D_INNER) + dir * D_INNER + d] =
                __float2bfloat16(y * (zv / (1.f + __expf(-zv))));
        }
    }
}

// ---------------- launch -----------------------------------------------------
extern "C" void kernel_launch(void* const* d_in, const int* in_sizes, int n_in,
                              void* d_out, int out_size) {
    const float* x    = (const float*)d_in[0];
    const float* bng  = (const float*)d_in[1];
    const float* bnb  = (const float*)d_in[2];
    const float* bnm  = (const float*)d_in[3];
    const float* bnv  = (const float*)d_in[4];
    const float* pw   = (const float*)d_in[5];
    const float* pb   = (const float*)d_in[6];
    const float* lpg  = (const float*)d_in[7];
    const float* lpb  = (const float*)d_in[8];
    const float* pos  = (const float*)d_in[9];
    const float* blg  = (const float*)d_in[10];
    const float* blb  = (const float*)d_in[11];
    const float* Wi   = (const float*)d_in[12];
    const float* cw   = (const float*)d_in[13];
    const float* cb   = (const float*)d_in[14];
    const float* Wx   = (const float*)d_in[15];
    const float* Wdt  = (const float*)d_in[16];
    const float* bdt  = (const float*)d_in[17];
    const float* Alog = (const float*)d_in[18];
    const float* Dv   = (const float*)d_in[19];
    const float* Wo   = (const float*)d_in[20];
    const float* flg  = (const float*)d_in[21];
    const float* flb  = (const float*)d_in[22];
    float* out = (float*)d_out;

    float *ph, *puz, *puc, *pproj, *ppwt;
    __nv_bfloat16 *phnb, *pysb, *pwib, *pwob;
    cudaGetSymbolAddress((void**)&ph,   g_h);
    cudaGetSymbolAddress((void**)&puz,  g_uz);
    cudaGetSymbolAddress((void**)&puc,  g_uc);
    cudaGetSymbolAddress((void**)&pproj,g_proj);
    cudaGetSymbolAddress((void**)&ppwt, g_pwt);
    cudaGetSymbolAddress((void**)&phnb, g_hnb);
    cudaGetSymbolAddress((void**)&pysb, g_ysb);
    cudaGetSymbolAddress((void**)&pwib, g_wib);
    cudaGetSymbolAddress((void**)&pwob, g_wob);

    static int attr_done = 0;
    if (!attr_done) {
        cudaFuncSetAttribute(k_mmab<128,128,2,4,0>,
                             cudaFuncAttributeMaxDynamicSharedMemorySize, MMAB_SMEM);
        cudaFuncSetAttribute(k_mmab<128,128,2,4,2>,
                             cudaFuncAttributeMaxDynamicSharedMemorySize, MMAB_SMEM);
        attr_done = 1;
    }

    // weight transpose-convert
    k_tb<<<dim3(2 * D_INNER / 32, D_MODEL / 32, 4), dim3(32, 8)>>>(
        Wi, pwib, D_MODEL, 2 * D_INNER);
    k_tb<<<dim3(D_MODEL / 32, 2 * D_INNER / 32, 2), dim3(32, 8)>>>(
        Wo, pwob, 2 * D_INNER, D_MODEL);
    k_tpw<<<KPATCH, D_MODEL>>>(pw, ppwt);

    k_patch<<<M_ROWS / PGROW, 512>>>(x, bng, bnb, bnm, bnv, pb, lpg, lpb, pos);

    for (int i = 0; i < 2; i++) {
        k_ln_bf<<<M_ROWS, 512>>>(ph, phnb, blg + i * D_MODEL, blb + i * D_MODEL);

        // in_proj both dirs: bf16 (4096,512)@(512,2048) -> g_uz[dir]
        k_mmab<128,128,2,4,0>
            <<<dim3(2 * D_INNER / 128, M_ROWS / 128, 2), 256, MMAB_SMEM>>>(
            phnb, D_MODEL, 0,
            pwib + (size_t)i * 2 * 2 * D_INNER * D_MODEL, D_MODEL,
            (long)2 * D_INNER * D_MODEL,
            puz, 2 * D_INNER, (long)M_ROWS * 2 * D_INNER,
            D_MODEL);

        // conv + SiLU both dirs (float4 over d)
        k_conv<<<dim3(B_SZ * D_INNER / 4 / 256, 1, 2), 256>>>(
            cw + (size_t)i * 2 * D_INNER * D_CONV, cb + (size_t)i * 2 * D_INNER);

        // x_proj both dirs: tf32 (4096,1024)@(1024,64) -> g_proj[dir]
        k_mma<64,64,2,2><<<dim3(1, M_ROWS / 64, 2), 128>>>(
            puc, D_INNER, (long)M_ROWS * D_INNER,
            Wx + (size_t)i * 2 * D_INNER * PROJW, PROJW, (long)D_INNER * PROJW,
            pproj, PROJW, (long)M_ROWS * PROJW,
            D_INNER);

        // fused dt_proj + scan both dirs -> g_ysb (bf16)
        k_scan<<<dim3(B_SZ, D_INNER / 256, 2), 256>>>(
            Wdt  + (size_t)i * 2 * DT_RANK * D_INNER,
            bdt  + (size_t)i * 2 * D_INNER,
            Alog + (size_t)i * 2 * D_INNER * D_STATE,
            Dv   + (size_t)i * 2 * D_INNER);

        // out_proj: bf16 (4096,2048)@(2048,512) += g_h  [BM=128]
        k_mmab<128,128,2,4,2>
            <<<dim3(D_MODEL / 128, M_ROWS / 128, 1), 256, MMAB_SMEM>>>(
            pysb, 2 * D_INNER, 0,
            pwob + (size_t)i * 2 * D_INNER * D_MODEL, 2 * D_INNER, 0,
            ph, D_MODEL, 0,
            2 * D_INNER);
    }
    k_ln<<<M_ROWS, 512>>>(ph, out, flg, flb);
}

// round 17
// speedup vs baseline: 1.7720x; 1.0408x over previous
#include <cuda_runtime.h>
#include <cuda_bf16.h>
#include <math.h>
#include <stdint.h>

#define B_SZ   256
#define C_IN   7
#define T_LEN  160
#define PATCH  10
#define L_TK   16
#define D_MODEL 512
#define D_INNER 1024
#define D_STATE 16
#define DT_RANK 32
#define D_CONV  4
#define M_ROWS (B_SZ * L_TK)          // 4096
#define PROJW  (DT_RANK + 2*D_STATE)  // 64
#define KPATCH (C_IN * PATCH)         // 70
#define PGROW  8                      // rows per patch CTA
#define EPS 1e-5f

// ---------------- scratch ----------------------------------------------------
__device__ float g_h  [M_ROWS * D_MODEL];
__device__ float g_uz [2 * M_ROWS * 2 * D_INNER];
__device__ float g_uc [2 * M_ROWS * D_INNER];
__device__ float g_proj[2 * M_ROWS * PROJW];
__device__ float g_pwt[KPATCH * D_MODEL];                    // transposed patch_w
__device__ __nv_bfloat16 g_hnb[M_ROWS * D_MODEL];
__device__ __nv_bfloat16 g_ucb[2 * M_ROWS * D_INNER];        // bf16 uc (x_proj A)
__device__ __nv_bfloat16 g_ysb[M_ROWS * 2 * D_INNER];        // [row][dir*1024+d]
__device__ __nv_bfloat16 g_wib[4 * 2 * D_INNER * D_MODEL];   // 4 x [2048][512]
__device__ __nv_bfloat16 g_wob[2 * 2 * D_INNER * D_MODEL];   // 2 x [512][2048]
__device__ __nv_bfloat16 g_wxb[4 * PROJW * D_INNER];         // 4 x [64][1024]

// ---------------- helpers ----------------------------------------------------
__device__ __forceinline__ void mma16(float* c, const uint32_t* a, const uint32_t* b) {
    asm volatile(
        "mma.sync.aligned.m16n8k16.row.col.f32.bf16.bf16.f32 "
        "{%0,%1,%2,%3},{%4,%5,%6,%7},{%8,%9},{%0,%1,%2,%3};"
        : "+f"(c[0]), "+f"(c[1]), "+f"(c[2]), "+f"(c[3])
        : "r"(a[0]), "r"(a[1]), "r"(a[2]), "r"(a[3]), "r"(b[0]), "r"(b[1]));
}
__device__ __forceinline__ void ldsm4(uint32_t& r0, uint32_t& r1, uint32_t& r2,
                                      uint32_t& r3, uint32_t addr) {
    asm volatile("ldmatrix.sync.aligned.m8n8.x4.shared.b16 {%0,%1,%2,%3}, [%4];"
                 : "=r"(r0), "=r"(r1), "=r"(r2), "=r"(r3) : "r"(addr));
}
__device__ __forceinline__ float softplusf(float v) {
    return fmaxf(v, 0.f) + log1pf(__expf(-fabsf(v)));
}
__device__ __forceinline__ void cp16(void* dst, const void* src) {
    uint32_t d = (uint32_t)__cvta_generic_to_shared(dst);
    asm volatile("cp.async.cg.shared.global [%0], [%1], 16;" :: "r"(d), "l"(src));
}
#define CP_COMMIT() asm volatile("cp.async.commit_group;")
#define CP_WAIT2()  asm volatile("cp.async.wait_group 2;")

typedef unsigned long long ull;
__device__ __forceinline__ ull pk2(float x, float y) {
    ull r; asm("mov.b64 %0, {%1,%2};" : "=l"(r) : "f"(x), "f"(y)); return r;
}
__device__ __forceinline__ void upk2(ull v, float& x, float& y) {
    asm("mov.b64 {%0,%1}, %2;" : "=f"(x), "=f"(y) : "l"(v));
}
__device__ __forceinline__ ull fma2(ull a, ull b, ull c) {
    ull d; asm("fma.rn.f32x2 %0, %1, %2, %3;" : "=l"(d) : "l"(a), "l"(b), "l"(c)); return d;
}
__device__ __forceinline__ ull mul2(ull a, ull b) {
    ull d; asm("mul.rn.f32x2 %0, %1, %2;" : "=l"(d) : "l"(a), "l"(b)); return d;
}

// fused mean/rstd for one 512-wide row, 2 barriers
__device__ __forceinline__ void ln_stats_512(float v, float* smS, float* smQ,
                                             float* smMV, float& mean, float& rstd) {
    int tid = threadIdx.x, warp = tid >> 5, lane = tid & 31;
    float s = v, q = v * v;
    #pragma unroll
    for (int o = 16; o; o >>= 1) {
        s += __shfl_xor_sync(0xffffffffu, s, o);
        q += __shfl_xor_sync(0xffffffffu, q, o);
    }
    if (lane == 0) { smS[warp] = s; smQ[warp] = q; }
    __syncthreads();
    if (warp == 0) {
        float s2 = (lane < 16) ? smS[lane] : 0.f;
        float q2 = (lane < 16) ? smQ[lane] : 0.f;
        #pragma unroll
        for (int o = 8; o; o >>= 1) {
            s2 += __shfl_xor_sync(0xffffffffu, s2, o);
            q2 += __shfl_xor_sync(0xffffffffu, q2, o);
        }
        if (lane == 0) {
            float m = s2 * (1.f / D_MODEL);
            float var = q2 * (1.f / D_MODEL) - m * m;
            smMV[0] = m;
            smMV[1] = rsqrtf(var + EPS);
        }
    }
    __syncthreads();
    mean = smMV[0];
    rstd = smMV[1];
}

// ---------------- transpose + convert weights to bf16 ------------------------
__global__ void k_tb(const float* __restrict__ src, __nv_bfloat16* __restrict__ dst,
                     int K, int N) {
    __shared__ __nv_bfloat16 t[32][33];
    long zo = (long)blockIdx.z * K * N;
    int n0 = blockIdx.x * 32, k0 = blockIdx.y * 32;
    for (int i = threadIdx.y; i < 32; i += 8)
        t[i][threadIdx.x] = __float2bfloat16(src[zo + (size_t)(k0 + i) * N + n0 + threadIdx.x]);
    __syncthreads();
    for (int i = threadIdx.y; i < 32; i += 8)
        dst[zo + (size_t)(n0 + i) * K + k0 + threadIdx.x] = t[threadIdx.x][i];
}

// ---------------- transpose patch_w [512][70] -> [70][512] -------------------
__global__ void k_tpw(const float* __restrict__ src, float* __restrict__ dst) {
    int k = blockIdx.x;                // 0..69
    int n = threadIdx.x;               // 0..511
    dst[k * D_MODEL + n] = src[(size_t)n * KPATCH + k];
}

// ---------------- 3-stage bf16 MMA GEMM with ldmatrix ------------------------
// A [M][K] bf16 row-major, B [N][K] bf16 row-major (pre-transposed weights).
// EPI: 0 = store fp32, 2 = accumulate fp32. Dynamic smem (3 stages).
template<int BM, int BN, int WARPS_M, int WARPS_N, int EPI>
__global__ void __launch_bounds__(WARPS_M * WARPS_N * 32)
k_mmab(const __nv_bfloat16* __restrict__ A, int lda, long strideAz,
       const __nv_bfloat16* __restrict__ Bg, int ldb, long strideBz,
       float* __restrict__ C, int ldc, long strideCz, int K) {
    constexpr int BK = 32;
    constexpr int LDP = 20;               // 80B row stride: 16B aligned, conflict-free
    constexpr int NS  = 3;
    constexpr int T  = WARPS_M * WARPS_N * 32;
    constexpr int WTM = BM / WARPS_M;
    constexpr int WTN = BN / WARPS_N;
    constexpr int MT  = WTM / 16;
    constexpr int NT  = WTN / 8;
    static_assert(NT % 2 == 0, "NT must be even for paired B ldmatrix");

    extern __shared__ uint32_t dyn[];
    typedef uint32_t ATile[BM][LDP];
    typedef uint32_t BTile[BN][LDP];
    ATile* As2 = (ATile*)dyn;
    BTile* Bs2 = (BTile*)(dyn + NS * BM * LDP);

    int tid = threadIdx.x, lane = tid & 31, wid = tid >> 5;
    int wm = wid % WARPS_M, wn = wid / WARPS_M;
    int m0 = blockIdx.y * BM, n0 = blockIdx.x * BN;
    int z = blockIdx.z;
    int tig = lane & 3, grp = lane >> 2;

    const __nv_bfloat16* Ap = A + (long)z * strideAz;
    const __nv_bfloat16* Bp = Bg + (long)z * strideBz;
    float* Cp = C + (long)z * strideCz;

    int a_row_off = (lane & 7) + ((lane >> 3) & 1) * 8;
    int a_col_off = ((lane >> 4) & 1) * 4;
    int b_row_off = (lane & 7) + ((lane >> 4) & 1) * 8;
    int b_col_off = ((lane >> 3) & 1) * 4;

    float acc[MT][NT][4];
    #pragma unroll
    for (int i = 0; i < MT; i++)
        #pragma unroll
        for (int j = 0; j < NT; j++)
            #pragma unroll
            for (int q = 0; q < 4; q++) acc[i][j][q] = 0.f;

    auto load_tiles = [&](int st, int k0) {
        #pragma unroll 2
        for (int idx = tid; idx < BM * 4; idx += T) {
            int m = idx >> 2, c = idx & 3;
            cp16(&As2[st][m][c * 4], Ap + (size_t)(m0 + m) * lda + k0 + c * 8);
        }
        #pragma unroll 2
        for (int idx = tid; idx < BN * 4; idx += T) {
            int n = idx >> 2, c = idx & 3;
            cp16(&Bs2[st][n][c * 4], Bp + (size_t)(n0 + n) * ldb + k0 + c * 8);
        }
    };

    int KT = K / BK;
    load_tiles(0, 0);
    CP_COMMIT();
    load_tiles(1, BK);
    CP_COMMIT();
    int st = 0;
    for (int kt = 0; kt < KT; kt++) {
        if (kt + 2 < KT) {
            int s2 = st + 2; if (s2 >= NS) s2 -= NS;
            load_tiles(s2, (kt + 2) * BK);
        }
        CP_COMMIT();
        CP_WAIT2();
        __syncthreads();

        uint32_t aBase = (uint32_t)__cvta_generic_to_shared(&As2[st][0][0]);
        uint32_t bBase = (uint32_t)__cvta_generic_to_shared(&Bs2[st][0][0]);
        #pragma unroll
        for (int ks = 0; ks < 2; ks++) {
            int pb = ks * 8;
            uint32_t afr[MT][4], bfr[NT][2];
            #pragma unroll
            for (int i = 0; i < MT; i++) {
                int r = wm * WTM + i * 16;
                uint32_t addr = aBase +
                    (uint32_t)(((r + a_row_off) * LDP + pb + a_col_off) * 4);
                ldsm4(afr[i][0], afr[i][1], afr[i][2], afr[i][3], addr);
            }
            #pragma unroll
            for (int j = 0; j < NT; j += 2) {
                int nb = wn * WTN + j * 8;
                uint32_t addr = bBase +
                    (uint32_t)(((nb + b_row_off) * LDP + pb + b_col_off) * 4);
                ldsm4(bfr[j][0], bfr[j][1], bfr[j + 1][0], bfr[j + 1][1], addr);
            }
            #pragma unroll
            for (int i = 0; i < MT; i++)
                #pragma unroll
                for (int j = 0; j < NT; j++)
                    mma16(acc[i][j], afr[i], bfr[j]);
        }
        __syncthreads();
        if (++st >= NS) st = 0;
    }

    #pragma unroll
    for (int i = 0; i < MT; i++) {
        #pragma unroll
        for (int half = 0; half < 2; half++) {
            int r = m0 + wm * WTM + i * 16 + grp + half * 8;
            #pragma unroll
            for (int j = 0; j < NT; j++) {
                int n = n0 + wn * WTN + j * 8 + tig * 2;
                float v0 = acc[i][j][half * 2 + 0];
                float v1 = acc[i][j][half * 2 + 1];
                float* cp = Cp + (size_t)r * ldc + n;
                if (EPI == 2) {
                    cp[0] += v0;
                    cp[1] += v1;
                } else {
                    *(float2*)cp = make_float2(v0, v1);
                }
            }
        }
    }
}
#define MMAB_SMEM (3 * (128 * 20 + 128 * 20) * 4)
#define XPROJ_SMEM (3 * (64 * 20 + 64 * 20) * 4)

// -------- patch embed + LN + pos: PGROW rows/CTA, parallel reductions --------
__global__ void __launch_bounds__(512)
k_patch(const float* __restrict__ x,
        const float* __restrict__ bng, const float* __restrict__ bnb,
        const float* __restrict__ bnm, const float* __restrict__ bnv,
        const float* __restrict__ pb,
        const float* __restrict__ lg,  const float* __restrict__ lb,
        const float* __restrict__ pos) {
    __shared__ float p[PGROW][KPATCH + 2];
    __shared__ float smS[PGROW][16], smQ[PGROW][16];
    __shared__ float smMV[PGROW][2];
    int row0 = blockIdx.x * PGROW, tid = threadIdx.x;
    int warp = tid >> 5, lane = tid & 31;

    for (int e = tid; e < PGROW * KPATCH; e += 512) {
        int g = e / KPATCH, k = e - g * KPATCH;
        int row = row0 + g;
        int b = row >> 4, l = row & 15;
        int c = k / PATCH, j = k - c * PATCH;
        float xv = x[(b * C_IN + c) * T_LEN + l * PATCH + j];
        p[g][k] = (xv - bnm[c]) * rsqrtf(bnv[c] + EPS) * bng[c] + bnb[c];
    }
    __syncthreads();

    float acc[PGROW];
    float bias = pb[tid];
    #pragma unroll
    for (int g = 0; g < PGROW; g++) acc[g] = bias;
    const float* wt = g_pwt + tid;
    #pragma unroll 2
    for (int k = 0; k < KPATCH; k++) {
        float w = wt[(size_t)k * D_MODEL];
        #pragma unroll
        for (int g = 0; g < PGROW; g++) acc[g] = fmaf(p[g][k], w, acc[g]);
    }

    #pragma unroll
    for (int g = 0; g < PGROW; g++) {
        float s = acc[g], q = acc[g] * acc[g];
        #pragma unroll
        for (int o = 16; o; o >>= 1) {
            s += __shfl_xor_sync(0xffffffffu, s, o);
            q += __shfl_xor_sync(0xffffffffu, q, o);
        }
        if (lane == 0) { smS[g][warp] = s; smQ[g][warp] = q; }
    }
    __syncthreads();
    if (warp < PGROW) {
        float s = (lane < 16) ? smS[warp][lane] : 0.f;
        float q = (lane < 16) ? smQ[warp][lane] : 0.f;
        #pragma unroll
        for (int o = 8; o; o >>= 1) {
            s += __shfl_xor_sync(0xffffffffu, s, o);
            q += __shfl_xor_sync(0xffffffffu, q, o);
        }
        if (lane == 0) {
            float mean = s * (1.f / D_MODEL);
            float var  = q * (1.f / D_MODEL) - mean * mean;
            smMV[warp][0] = mean;
            smMV[warp][1] = rsqrtf(var + EPS);
        }
    }
    __syncthreads();

    float gv = lg[tid], bv = lb[tid];
    #pragma unroll
    for (int g = 0; g < PGROW; g++) {
        int row = row0 + g;
        int l = row & 15;
        g_h[(size_t)row * D_MODEL + tid] =
            (acc[g] - smMV[g][0]) * smMV[g][1] * gv + bv + pos[l * D_MODEL + tid];
    }
}

// ---------------- LayerNorm: fp32 in -> bf16 out (2 barriers) ----------------
__global__ void k_ln_bf(const float* __restrict__ in, __nv_bfloat16* __restrict__ out,
                        const float* __restrict__ g, const float* __restrict__ b) {
    __shared__ float smS[16], smQ[16], smMV[2];
    int row = blockIdx.x, tid = threadIdx.x;
    float v = in[row * D_MODEL + tid];
    float mean, rstd;
    ln_stats_512(v, smS, smQ, smMV, mean, rstd);
    out[row * D_MODEL + tid] =
        __float2bfloat16((v - mean) * rstd * g[tid] + b[tid]);
}

// ---------------- LayerNorm: fp32 -> fp32 (final, 2 barriers) ----------------
__global__ void k_ln(const float* __restrict__ in, float* __restrict__ out,
                     const float* __restrict__ g, const float* __restrict__ b) {
    __shared__ float smS[16], smQ[16], smMV[2];
    int row = blockIdx.x, tid = threadIdx.x;
    float v = in[row * D_MODEL + tid];
    float mean, rstd;
    ln_stats_512(v, smS, smQ, smMV, mean, rstd);
    out[row * D_MODEL + tid] = (v - mean) * rstd * g[tid] + b[tid];
}

// ------- conv + SiLU, both dirs, float4; writes fp32 uc + bf16 ucb -----------
__global__ void __launch_bounds__(256)
k_conv(const float* __restrict__ cw, const float* __restrict__ cb) {
    int dir = blockIdx.z;
    int idx = blockIdx.x * 256 + threadIdx.x;    // B_SZ * (D_INNER/4)
    int b = idx >> 8;
    int d = (idx & 255) * 4;
    const float4* u = (const float4*)(g_uz + (size_t)dir * M_ROWS * 2 * D_INNER
                                      + (size_t)(b * L_TK) * (2 * D_INNER) + d);
    float4* o = (float4*)(g_uc + (size_t)dir * M_ROWS * D_INNER
                          + (size_t)(b * L_TK) * D_INNER + d);
    ull* ob = (ull*)(g_ucb + (size_t)dir * M_ROWS * D_INNER
                     + (size_t)(b * L_TK) * D_INNER + d);
    const float* cwd = cw + (size_t)dir * D_INNER * D_CONV;
    const float* cbd = cb + (size_t)dir * D_INNER;
    float4 w0 = *(const float4*)(cwd + (d + 0) * D_CONV);
    float4 w1 = *(const float4*)(cwd + (d + 1) * D_CONV);
    float4 w2 = *(const float4*)(cwd + (d + 2) * D_CONV);
    float4 w3 = *(const float4*)(cwd + (d + 3) * D_CONV);
    float4 bias = *(const float4*)(cbd + d);
    float4 h0 = make_float4(0.f, 0.f, 0.f, 0.f);
    float4 h1 = h0, h2 = h0;
    #pragma unroll
    for (int l = 0; l < L_TK; l++) {
        int j = dir ? (15 - l) : l;
        float4 cur = u[(size_t)j * (2 * D_INNER / 4)];
        float a0 = bias.x, a1 = bias.y, a2 = bias.z, a3 = bias.w;
        a0 = fmaf(w0.x, h0.x, a0); a0 = fmaf(w0.y, h1.x, a0);
        a0 = fmaf(w0.z, h2.x, a0); a0 = fmaf(w0.w, cur.x, a0);
        a1 = fmaf(w1.x, h0.y, a1); a1 = fmaf(w1.y, h1.y, a1);
        a1 = fmaf(w1.z, h2.y, a1); a1 = fmaf(w1.w, cur.y, a1);
        a2 = fmaf(w2.x, h0.z, a2); a2 = fmaf(w2.y, h1.z, a2);
        a2 = fmaf(w2.z, h2.z, a2); a2 = fmaf(w2.w, cur.z, a2);
        a3 = fmaf(w3.x, h0.w, a3); a3 = fmaf(w3.y, h1.w, a3);
        a3 = fmaf(w3.z, h2.w, a3); a3 = fmaf(w3.w, cur.w, a3);
        float4 r;
        r.x = a0 / (1.f + __expf(-a0));
        r.y = a1 / (1.f + __expf(-a1));
        r.z = a2 / (1.f + __expf(-a2));
        r.w = a3 / (1.f + __expf(-a3));
        o[(size_t)l * (D_INNER / 4)] = r;
        __nv_bfloat162 lo = __floats2bfloat162_rn(r.x, r.y);
        __nv_bfloat162 hi = __floats2bfloat162_rn(r.z, r.w);
        ull pkd;
        asm("mov.b64 %0, {%1,%2};" : "=l"(pkd)
            : "r"(*(uint32_t*)&lo), "r"(*(uint32_t*)&hi));
        ob[(size_t)l * (D_INNER / 4)] = pkd;
        h0 = h1; h1 = h2; h2 = cur;
    }
}

// ---------------- fused dt_proj + softplus + scan + D skip + gate ------------
__global__ void k_scan(const float* __restrict__ Wdt, const float* __restrict__ bdt,
                       const float* __restrict__ Alog, const float* __restrict__ Dv) {
    __shared__ ull B2[L_TK][8], C2[L_TK][8];
    __shared__ float dtr[L_TK][DT_RANK];
    int dir = blockIdx.z;
    int b = blockIdx.x;
    int tid = threadIdx.x;
    int d = blockIdx.y * 256 + tid;

    const float* proj = g_proj + (size_t)dir * M_ROWS * PROJW;
    const float* ucp  = g_uc   + (size_t)dir * M_ROWS * D_INNER;
    const float* uzp  = g_uz   + (size_t)dir * M_ROWS * 2 * D_INNER;
    const float* Wdtd = Wdt  + (size_t)dir * DT_RANK * D_INNER;
    const float* bdtd = bdt  + (size_t)dir * D_INNER;
    const float* Al   = Alog + (size_t)dir * D_INNER * D_STATE;
    const float* Dp   = Dv   + (size_t)dir * D_INNER;

    for (int e = tid; e < L_TK * 8; e += 256) {
        int l = e >> 3, p = e & 7;
        const float* pr = proj + (size_t)(b * L_TK + l) * PROJW;
        float2 vb = *(const float2*)(pr + DT_RANK + p * 2);
        float2 vc = *(const float2*)(pr + DT_RANK + D_STATE + p * 2);
        B2[l][p] = pk2(vb.x, vb.y);
        C2[l][p] = pk2(vc.x, vc.y);
    }
    for (int e = tid; e < L_TK * DT_RANK; e += 256) {
        int l = e >> 5, k = e & 31;
        dtr[l][k] = proj[(size_t)(b * L_TK + l) * PROJW + k];
    }
    __syncthreads();

    float dtv[L_TK];
    {
        float bias = bdtd[d];
        #pragma unroll
        for (int l = 0; l < L_TK; l++) dtv[l] = bias;
        #pragma unroll 4
        for (int k = 0; k < DT_RANK; k++) {
            float w = Wdtd[(size_t)k * D_INNER + d];
            #pragma unroll
            for (int l = 0; l < L_TK; l++) dtv[l] = fmaf(dtr[l][k], w, dtv[l]);
        }
        #pragma unroll
        for (int l = 0; l < L_TK; l++) dtv[l] = softplusf(dtv[l]);
    }

    float A[D_STATE];
    bool ok = true;
    #pragma unroll
    for (int n = 0; n < D_STATE; n++) {
        A[n] = -__expf(Al[(size_t)d * D_STATE + n]);
        ok = ok && (fabsf(A[n] + (float)(n + 1)) < 2e-3f);
    }
    float Dd = Dp[d];

    if (ok) {
        ull st[8];
        #pragma unroll
        for (int p = 0; p < 8; p++) st[p] = pk2(0.f, 0.f);
        for (int l = 0; l < L_TK; l++) {
            int rp = b * L_TK + l;
            int rn = b * L_TK + (dir ? (15 - l) : l);
            float dt = dtv[l];
            float u  = ucp[(size_t)rp * D_INNER + d];
            float du = dt * u;
            float q  = __expf(-dt);
            float qq = q * q;
            ull w    = pk2(q, qq);
            ull step = pk2(qq, qq);
            ull du2  = pk2(du, du);
            ull y2   = pk2(0.f, 0.f);
            #pragma unroll
            for (int p = 0; p < 8; p++) {
                st[p] = fma2(st[p], w, mul2(du2, B2[l][p]));
                y2 = fma2(st[p], C2[l][p], y2);
                w = mul2(w, step);
            }
            float ylo, yhi;
            upk2(y2, ylo, yhi);
            float y = ylo + yhi + u * Dd;
            float zv = uzp[(size_t)rn * (2 * D_INNER) + D_INNER + d];
            g_ysb[(size_t)rn * (2 * D_INNER) + dir * D_INNER + d] =
                __float2bfloat16(y * (zv / (1.f + __expf(-zv))));
        }
    } else {
        float st[D_STATE];
        #pragma unroll
        for (int n = 0; n < D_STATE; n++) st[n] = 0.f;
        for (int l = 0; l < L_TK; l++) {
            int rp = b * L_TK + l;
            int rn = b * L_TK + (dir ? (15 - l) : l);
            float dt = dtv[l];
            float u  = ucp[(size_t)rp * D_INNER + d];
            float du = dt * u;
            float y = 0.f;
            #pragma unroll
            for (int n = 0; n < D_STATE; n++) {
                float blo, bhi, clo, chi;
                upk2(B2[l][n >> 1], blo, bhi);
                upk2(C2[l][n >> 1], clo, chi);
                float Bv = (n & 1) ? bhi : blo;
                float Cv = (n & 1) ? chi : clo;
                float s = fmaf(st[n], __expf(dt * A[n]), du * Bv);
                st[n] = s;
                y = fmaf(s, Cv, y);
            }
            y = fmaf(u, Dd, y);
            float zv = uzp[(size_t)rn * (2 * D_INNER) + D_INNER + d];
            g_ysb[(size_t)rn * (2 * D_INNER) + dir * D_INNER + d] =
                __float2bfloat16(y * (zv / (1.f + __expf(-zv))));
        }
    }
}

// ---------------- launch -----------------------------------------------------
extern "C" void kernel_launch(void* const* d_in, const int* in_sizes, int n_in,
                              void* d_out, int out_size) {
    const float* x    = (const float*)d_in[0];
    const float* bng  = (const float*)d_in[1];
    const float* bnb  = (const float*)d_in[2];
    const float* bnm  = (const float*)d_in[3];
    const float* bnv  = (const float*)d_in[4];
    const float* pw   = (const float*)d_in[5];
    const float* pb   = (const float*)d_in[6];
    const float* lpg  = (const float*)d_in[7];
    const float* lpb  = (const float*)d_in[8];
    const float* pos  = (const float*)d_in[9];
    const float* blg  = (const float*)d_in[10];
    const float* blb  = (const float*)d_in[11];
    const float* Wi   = (const float*)d_in[12];
    const float* cw   = (const float*)d_in[13];
    const float* cb   = (const float*)d_in[14];
    const float* Wx   = (const float*)d_in[15];
    const float* Wdt  = (const float*)d_in[16];
    const float* bdt  = (const float*)d_in[17];
    const float* Alog = (const float*)d_in[18];
    const float* Dv   = (const float*)d_in[19];
    const float* Wo   = (const float*)d_in[20];
    const float* flg  = (const float*)d_in[21];
    const float* flb  = (const float*)d_in[22];
    float* out = (float*)d_out;

    float *ph, *puz, *pproj, *ppwt;
    __nv_bfloat16 *phnb, *pucb, *pysb, *pwib, *pwob, *pwxb;
    cudaGetSymbolAddress((void**)&ph,   g_h);
    cudaGetSymbolAddress((void**)&puz,  g_uz);
    cudaGetSymbolAddress((void**)&pproj,g_proj);
    cudaGetSymbolAddress((void**)&ppwt, g_pwt);
    cudaGetSymbolAddress((void**)&phnb, g_hnb);
    cudaGetSymbolAddress((void**)&pucb, g_ucb);
    cudaGetSymbolAddress((void**)&pysb, g_ysb);
    cudaGetSymbolAddress((void**)&pwib, g_wib);
    cudaGetSymbolAddress((void**)&pwob, g_wob);
    cudaGetSymbolAddress((void**)&pwxb, g_wxb);

    static int attr_done = 0;
    if (!attr_done) {
        cudaFuncSetAttribute(k_mmab<128,128,2,4,0>,
                             cudaFuncAttributeMaxDynamicSharedMemorySize, MMAB_SMEM);
        cudaFuncSetAttribute(k_mmab<128,128,2,4,2>,
                             cudaFuncAttributeMaxDynamicSharedMemorySize, MMAB_SMEM);
        cudaFuncSetAttribute(k_mmab<64,64,2,2,0>,
                             cudaFuncAttributeMaxDynamicSharedMemorySize, XPROJ_SMEM);
        attr_done = 1;
    }

    // weight transpose-convert
    k_tb<<<dim3(2 * D_INNER / 32, D_MODEL / 32, 4), dim3(32, 8)>>>(
        Wi, pwib, D_MODEL, 2 * D_INNER);
    k_tb<<<dim3(D_MODEL / 32, 2 * D_INNER / 32, 2), dim3(32, 8)>>>(
        Wo, pwob, 2 * D_INNER, D_MODEL);
    k_tb<<<dim3(PROJW / 32, D_INNER / 32, 4), dim3(32, 8)>>>(
        Wx, pwxb, D_INNER, PROJW);
    k_tpw<<<KPATCH, D_MODEL>>>(pw, ppwt);

    k_patch<<<M_ROWS / PGROW, 512>>>(x, bng, bnb, bnm, bnv, pb, lpg, lpb, pos);

    for (int i = 0; i < 2; i++) {
        k_ln_bf<<<M_ROWS, 512>>>(ph, phnb, blg + i * D_MODEL, blb + i * D_MODEL);

        // in_proj both dirs: bf16 (4096,512)@(512,2048) -> g_uz[dir]
        k_mmab<128,128,2,4,0>
            <<<dim3(2 * D_INNER / 128, M_ROWS / 128, 2), 256, MMAB_SMEM>>>(
            phnb, D_MODEL, 0,
            pwib + (size_t)i * 2 * 2 * D_INNER * D_MODEL, D_MODEL,
            (long)2 * D_INNER * D_MODEL,
            puz, 2 * D_INNER, (long)M_ROWS * 2 * D_INNER,
            D_MODEL);

        // conv + SiLU both dirs (float4; fp32 uc + bf16 ucb)
        k_conv<<<dim3(B_SZ * D_INNER / 4 / 256, 1, 2), 256>>>(
            cw + (size_t)i * 2 * D_INNER * D_CONV, cb + (size_t)i * 2 * D_INNER);

        // x_proj both dirs: bf16 (4096,1024)@(1024,64) -> g_proj[dir]
        k_mmab<64,64,2,2,0>
            <<<dim3(1, M_ROWS / 64, 2), 128, XPROJ_SMEM>>>(
            pucb, D_INNER, (long)M_ROWS * D_INNER,
            pwxb + (size_t)i * 2 * PROJW * D_INNER, D_INNER,
            (long)PROJW * D_INNER,
            pproj, PROJW, (long)M_ROWS * PROJW,
            D_INNER);

        // fused dt_proj + scan both dirs -> g_ysb (bf16)
        k_scan<<<dim3(B_SZ, D_INNER / 256, 2), 256>>>(
            Wdt  + (size_t)i * 2 * DT_RANK * D_INNER,
            bdt  + (size_t)i * 2 * D_INNER,
            Alog + (size_t)i * 2 * D_INNER * D_STATE,
            Dv   + (size_t)i * 2 * D_INNER);

        // out_proj: bf16 (4096,2048)@(2048,512) += g_h
        k_mmab<128,128,2,4,2>
            <<<dim3(D_MODEL / 128, M_ROWS / 128, 1), 256, MMAB_SMEM>>>(
            pysb, 2 * D_INNER, 0,
            pwob + (size_t)i * 2 * D_INNER * D_MODEL, 2 * D_INNER, 0,
            ph, D_MODEL, 0,
            2 * D_INNER);
    }
    k_ln<<<M_ROWS, 512>>>(ph, out, flg, flb);
}